// round 1
// baseline (speedup 1.0000x reference)
#include <cuda_runtime.h>
#include <cuda_bf16.h>
#include <math.h>

// ---------------- problem constants ----------------
static const int B_   = 2;
static const int L_   = 2048;
static const int DM   = 256;    // D_MODEL
static const int DS   = 128;    // D_STATE
static const int DI   = 1024;   // D_INNER
static const int NH   = 16;     // NHEADS
static const int HD   = 64;     // HEADDIM
static const int CD   = 1280;   // CONV_DIM
static const int DIP  = 2320;   // D_IN_PROJ
static const int CH   = 256;    // CHUNK
static const int NC   = 8;      // chunks per sequence
#define GN_EPS 1.1920928955078125e-07f
#define RMS_EPS 1e-5f

// ---------------- scratch (device globals, no allocs) ----------------
__device__ float g_t    [B_*L_*DM];          // normalized, transposed input (b,l,d)
__device__ float g_zx   [B_*L_*DIP];         // in-proj output
__device__ float g_xbc  [B_*L_*CD];          // conv+silu output
__device__ float g_dt   [B_*L_*NH];          // softplus dt
__device__ float g_acs  [B_*NH*L_];          // per-chunk inclusive cumsum of A
__device__ float g_cb   [B_*NC*CH*CH];       // C @ B^T per chunk
__device__ float g_st   [B_*NC*NH*HD*DS];    // per-chunk end states
__device__ float g_pv   [B_*NC*NH*HD*DS];    // incoming state per chunk
__device__ float g_y    [B_*L_*DI];          // mamba inner output
__device__ float g_r    [B_*L_*2*DM];        // concat(fwd+t, bwd+t)
__device__ float g_pr   [B_*L_*DM];          // gemm scratch
__device__ float g_stats[4];                 // mu, rsqrt per batch

__device__ __forceinline__ float siluf(float x) { return x / (1.f + expf(-x)); }
__device__ __forceinline__ float softplusf(float x) { return x > 20.f ? x : log1pf(expf(x)); }

// ---------------- GroupNorm stats (1 block per batch) ----------------
__global__ void gn_stats_k(const float* __restrict__ x, float* __restrict__ stats) {
    int b = blockIdx.x;
    const float* xb = x + (size_t)b * DM * L_;
    double s = 0.0, ss = 0.0;
    for (int i = threadIdx.x; i < DM * L_; i += blockDim.x) {
        double v = xb[i]; s += v; ss += v * v;
    }
    __shared__ double sh[512], sh2[512];
    sh[threadIdx.x] = s; sh2[threadIdx.x] = ss;
    __syncthreads();
    for (int o = 256; o > 0; o >>= 1) {
        if ((int)threadIdx.x < o) { sh[threadIdx.x] += sh[threadIdx.x + o]; sh2[threadIdx.x] += sh2[threadIdx.x + o]; }
        __syncthreads();
    }
    if (threadIdx.x == 0) {
        double n = (double)DM * L_;
        double mu = sh[0] / n;
        double var = sh2[0] / n - mu * mu;
        stats[b * 2 + 0] = (float)mu;
        stats[b * 2 + 1] = rsqrtf((float)var + GN_EPS);
    }
}

// ---------------- GroupNorm apply + transpose (B,D,L)->(B,L,D) ----------------
__global__ void gn_apply_k(const float* __restrict__ x, const float* __restrict__ gw,
                           const float* __restrict__ gb, const float* __restrict__ stats,
                           float* __restrict__ t) {
    int b = blockIdx.z;
    __shared__ float tile[32][33];
    int l0 = blockIdx.x * 32, d0 = blockIdx.y * 32;
    float mu = stats[b * 2], rs = stats[b * 2 + 1];
#pragma unroll
    for (int r = 0; r < 4; r++) {
        int d = d0 + threadIdx.y + r * 8;
        tile[threadIdx.y + r * 8][threadIdx.x] = x[((size_t)b * DM + d) * L_ + l0 + threadIdx.x];
    }
    __syncthreads();
    int d = d0 + threadIdx.x;
    float w = gw[d], bb = gb[d];
#pragma unroll
    for (int r = 0; r < 4; r++) {
        int l = l0 + threadIdx.y + r * 8;
        t[((size_t)b * L_ + l) * DM + d] = (tile[threadIdx.x][threadIdx.y + r * 8] - mu) * rs * w + bb;
    }
}

// ---------------- generic strided-batched NT GEMM ----------------
// C[m,n] = sum_k A[m*lda+k] * Bp[n*ldb+k]; optional time-reversal of A rows (revL = seq len)
__global__ void gemm_nt(const float* __restrict__ A, const float* __restrict__ Bp,
                        float* __restrict__ C, int M, int N, int K,
                        int lda, int ldb, int ldc,
                        long long sA, long long sB, long long sC, int revL) {
    int z = blockIdx.z;
    A += z * sA; Bp += z * sB; C += z * sC;
    __shared__ float As[16][65];
    __shared__ float Bs[16][65];
    int m0 = blockIdx.y * 64, n0 = blockIdx.x * 64;
    int tid = threadIdx.x;
    int tx = tid & 15, ty = tid >> 4;
    float acc[4][4] = {};
    for (int k0 = 0; k0 < K; k0 += 16) {
#pragma unroll
        for (int i = 0; i < 4; i++) {
            int e = tid + i * 256;
            int mm = e >> 4, kk = e & 15;
            int gm = m0 + mm;
            float v = 0.f;
            if (gm < M) {
                int row = gm;
                if (revL) { int bb = gm / revL; int ll = gm % revL; row = bb * revL + (revL - 1 - ll); }
                v = A[(long long)row * lda + k0 + kk];
            }
            As[kk][mm] = v;
        }
#pragma unroll
        for (int i = 0; i < 4; i++) {
            int e = tid + i * 256;
            int nn = e >> 4, kk = e & 15;
            int gn = n0 + nn;
            Bs[kk][nn] = (gn < N) ? Bp[(long long)gn * ldb + k0 + kk] : 0.f;
        }
        __syncthreads();
#pragma unroll
        for (int kk = 0; kk < 16; kk++) {
            float av[4], bv[4];
#pragma unroll
            for (int i = 0; i < 4; i++) av[i] = As[kk][ty * 4 + i];
#pragma unroll
            for (int j = 0; j < 4; j++) bv[j] = Bs[kk][tx * 4 + j];
#pragma unroll
            for (int i = 0; i < 4; i++)
#pragma unroll
                for (int j = 0; j < 4; j++) acc[i][j] += av[i] * bv[j];
        }
        __syncthreads();
    }
#pragma unroll
    for (int i = 0; i < 4; i++) {
        int gm = m0 + ty * 4 + i;
        if (gm < M) {
#pragma unroll
            for (int j = 0; j < 4; j++) {
                int gn = n0 + tx * 4 + j;
                if (gn < N) C[(long long)gm * ldc + gn] = acc[i][j];
            }
        }
    }
}

// ---------------- depthwise conv (k=4, causal) + SiLU ----------------
__global__ void conv_silu_k(const float* __restrict__ zx, const float* __restrict__ cw,
                            const float* __restrict__ cb, float* __restrict__ xbc) {
    int idx = blockIdx.x * blockDim.x + threadIdx.x;
    if (idx >= B_ * L_ * CD) return;
    int ch = idx % CD;
    int l  = (idx / CD) % L_;
    int b  = idx / (CD * L_);
    float acc = cb[ch];
#pragma unroll
    for (int k = 0; k < 4; k++) {
        int lp = l - 3 + k;
        if (lp >= 0) acc += cw[ch * 4 + k] * zx[(size_t)(b * L_ + lp) * DIP + DI + ch];
    }
    xbc[idx] = siluf(acc);
}

// ---------------- dt = softplus(raw + bias); A cumsum per chunk ----------------
__global__ void dt_scan_k(const float* __restrict__ zx, const float* __restrict__ dt_bias,
                          const float* __restrict__ A_log, float* __restrict__ dt,
                          float* __restrict__ acs) {
    int bi = blockIdx.x;
    int c = bi % NC, h = (bi / NC) % NH, b = bi / (NC * NH);
    int l = threadIdx.x;
    int gl = c * CH + l;
    int row = b * L_ + gl;
    float v = zx[(size_t)row * DIP + (DIP - NH) + h] + dt_bias[h];
    float dtv = softplusf(v);
    dt[row * NH + h] = dtv;
    float a = -expf(A_log[h]) * dtv;
    __shared__ float sb[CH];
    sb[l] = a;
    __syncthreads();
    for (int off = 1; off < CH; off <<= 1) {
        float tv = (l >= off) ? sb[l - off] : 0.f;
        __syncthreads();
        sb[l] += tv;
        __syncthreads();
    }
    acs[(b * NH + h) * L_ + gl] = sb[l];
}

// ---------------- per-chunk end state: st[p,n] = sum_l w[l]*x[l,p]*B[l,n] ----------------
__global__ void states_k(const float* __restrict__ xbc, const float* __restrict__ dt,
                         const float* __restrict__ acs, float* __restrict__ st) {
    int h = blockIdx.x, c = blockIdx.y, b = blockIdx.z;
    int tid = threadIdx.x;
    __shared__ float Xs[32][65];
    __shared__ float Bs[32][129];
    int acsbase = (b * NH + h) * L_ + c * CH;
    float csLast = acs[acsbase + CH - 1];
    float accv[32];
#pragma unroll
    for (int j = 0; j < 32; j++) accv[j] = 0.f;
    int p = tid & 63, ng = tid >> 6;
    for (int s0 = 0; s0 < CH; s0 += 32) {
#pragma unroll
        for (int i = 0; i < 8; i++) {
            int e = tid + i * 256;
            int pp = e & 63, ss = e >> 6;
            int row = b * L_ + c * CH + s0 + ss;
            float w = dt[row * NH + h] * expf(csLast - acs[acsbase + s0 + ss]);
            Xs[ss][pp] = xbc[(size_t)row * CD + h * HD + pp] * w;
        }
#pragma unroll
        for (int i = 0; i < 16; i++) {
            int e = tid + i * 256;
            int nn = e & 127, ss = e >> 7;
            int row = b * L_ + c * CH + s0 + ss;
            Bs[ss][nn] = xbc[(size_t)row * CD + DI + nn];
        }
        __syncthreads();
#pragma unroll
        for (int ss = 0; ss < 32; ss++) {
            float xv = Xs[ss][p];
#pragma unroll
            for (int j = 0; j < 32; j++) accv[j] += xv * Bs[ss][ng * 32 + j];
        }
        __syncthreads();
    }
    size_t base = ((size_t)((b * NC + c) * NH + h) * HD + p) * DS + ng * 32;
#pragma unroll
    for (int j = 0; j < 32; j++) st[base + j] = accv[j];
}

// ---------------- inter-chunk recurrence ----------------
__global__ void chunkscan_k(const float* __restrict__ st, const float* __restrict__ acs,
                            float* __restrict__ pv) {
    int idx = blockIdx.x * blockDim.x + threadIdx.x;  // B*NH*HD*DS threads
    int n = idx & (DS - 1);
    int p = (idx >> 7) & (HD - 1);
    int h = (idx >> 13) & (NH - 1);
    int b = idx >> 17;
    float S = 0.f;
    for (int c = 0; c < NC; c++) {
        size_t off = ((size_t)((b * NC + c) * NH + h) * HD + p) * DS + n;
        pv[off] = S;
        float at = acs[(b * NH + h) * L_ + c * CH + CH - 1];
        S = S * expf(at) + st[off];
    }
}

// ---------------- Y = diag(masked decayed CB @ X) + exp(cs)*C@prev^T + x*D ----------------
__global__ void ssd_y_k(const float* __restrict__ xbc, const float* __restrict__ dt,
                        const float* __restrict__ acs, const float* __restrict__ cb,
                        const float* __restrict__ pv, const float* __restrict__ Dh,
                        float* __restrict__ y) {
    int lt = blockIdx.x, h = blockIdx.y, bc = blockIdx.z;
    int c = bc % NC, b = bc / NC;
    int tid = threadIdx.x;
    int tx = tid & 15, ty = tid >> 4;
    __shared__ float Ws[64][33];
    __shared__ float Xs[32][65];
    __shared__ float csl[64], css[32];
    int l0 = lt * 64;
    int acsbase = (b * NH + h) * L_ + c * CH;
    if (tid < 64) csl[tid] = acs[acsbase + l0 + tid];
    const float* cbb = cb + (size_t)(b * NC + c) * CH * CH;
    float acc[4][4] = {};
    float acc2[4][4] = {};
    int nst = 2 * lt + 2;
    for (int st = 0; st < nst; st++) {
        int s0 = st * 32;
        __syncthreads();
        if (tid < 32) css[tid] = acs[acsbase + s0 + tid];
#pragma unroll
        for (int i = 0; i < 8; i++) {
            int e = tid + i * 256;
            int pp = e & 63, ss = e >> 6;
            int row = b * L_ + c * CH + s0 + ss;
            Xs[ss][pp] = xbc[(size_t)row * CD + h * HD + pp] * dt[row * NH + h];
        }
        __syncthreads();
#pragma unroll
        for (int i = 0; i < 8; i++) {
            int e = tid + i * 256;
            int j = e & 31, ii = e >> 5;
            float w = 0.f;
            if (s0 + j <= l0 + ii) w = expf(csl[ii] - css[j]) * cbb[(l0 + ii) * CH + s0 + j];
            Ws[ii][j] = w;
        }
        __syncthreads();
#pragma unroll
        for (int kk = 0; kk < 32; kk++) {
            float av[4], bv[4];
#pragma unroll
            for (int i = 0; i < 4; i++) av[i] = Ws[ty * 4 + i][kk];
#pragma unroll
            for (int j = 0; j < 4; j++) bv[j] = Xs[kk][tx * 4 + j];
#pragma unroll
            for (int i = 0; i < 4; i++)
#pragma unroll
                for (int j = 0; j < 4; j++) acc[i][j] += av[i] * bv[j];
        }
    }
    const float* pvb = pv + (size_t)((b * NC + c) * NH + h) * HD * DS;
    for (int nt = 0; nt < 4; nt++) {
        int n0 = nt * 32;
        __syncthreads();
#pragma unroll
        for (int i = 0; i < 8; i++) {
            int e = tid + i * 256;
            int j = e & 31, ii = e >> 5;
            int row = b * L_ + c * CH + l0 + ii;
            Ws[ii][j] = xbc[(size_t)row * CD + DI + DS + n0 + j];
        }
#pragma unroll
        for (int i = 0; i < 8; i++) {
            int e = tid + i * 256;
            int j = e & 31, pp = e >> 5;
            Xs[j][pp] = pvb[pp * DS + n0 + j];
        }
        __syncthreads();
#pragma unroll
        for (int kk = 0; kk < 32; kk++) {
            float av[4], bv[4];
#pragma unroll
            for (int i = 0; i < 4; i++) av[i] = Ws[ty * 4 + i][kk];
#pragma unroll
            for (int j = 0; j < 4; j++) bv[j] = Xs[kk][tx * 4 + j];
#pragma unroll
            for (int i = 0; i < 4; i++)
#pragma unroll
                for (int j = 0; j < 4; j++) acc2[i][j] += av[i] * bv[j];
        }
    }
    float dh = Dh[h];
#pragma unroll
    for (int i = 0; i < 4; i++) {
        int ll = l0 + ty * 4 + i;
        int row = b * L_ + c * CH + ll;
        float sd = expf(csl[ty * 4 + i]);
#pragma unroll
        for (int j = 0; j < 4; j++) {
            int pp = tx * 4 + j;
            float xraw = xbc[(size_t)row * CD + h * HD + pp];
            y[(size_t)row * DI + h * HD + pp] = acc[i][j] + sd * acc2[i][j] + xraw * dh;
        }
    }
}

// ---------------- gating (silu(z)) + RMSNorm ----------------
__global__ void gate_rms_k(float* __restrict__ y, const float* __restrict__ zx,
                           const float* __restrict__ nw) {
    int row = blockIdx.x;
    int tid = threadIdx.x;
    float v[4];
    float ss = 0.f;
#pragma unroll
    for (int i = 0; i < 4; i++) {
        int d = i * 256 + tid;
        float z = zx[(size_t)row * DIP + d];
        float yy = y[(size_t)row * DI + d] * siluf(z);
        v[i] = yy;
        ss += yy * yy;
    }
    __shared__ float sh[256];
    sh[tid] = ss;
    __syncthreads();
    for (int o = 128; o > 0; o >>= 1) {
        if (tid < o) sh[tid] += sh[tid + o];
        __syncthreads();
    }
    float scale = rsqrtf(sh[0] / DI + RMS_EPS);
#pragma unroll
    for (int i = 0; i < 4; i++) {
        int d = i * 256 + tid;
        y[(size_t)row * DI + d] = v[i] * scale * nw[d];
    }
}

// ---------------- out-proj epilogue: map time, add residual t ----------------
__global__ void outproj_epi_k(const float* __restrict__ pr, const float* __restrict__ t,
                              float* __restrict__ r, int dir) {
    int idx = blockIdx.x * blockDim.x + threadIdx.x;
    if (idx >= B_ * L_ * DM) return;
    int d = idx % DM;
    int l = (idx / DM) % L_;
    int b = idx / (DM * L_);
    int ltm = dir ? (L_ - 1 - l) : l;
    r[(size_t)(b * L_ + ltm) * (2 * DM) + dir * DM + d] = pr[idx] + t[(size_t)(b * L_ + ltm) * DM + d];
}

// ---------------- final epilogue: transpose back, add x + bias ----------------
__global__ void final_epi_k(const float* __restrict__ pr, const float* __restrict__ x,
                            const float* __restrict__ pb, float* __restrict__ out) {
    int idx = blockIdx.x * blockDim.x + threadIdx.x;
    if (idx >= B_ * DM * L_) return;
    int l = idx % L_;
    int d = (idx / L_) % DM;
    int b = idx / (L_ * DM);
    out[idx] = x[idx] + pr[(size_t)(b * L_ + l) * DM + d] + pb[d];
}

// ---------------- launch ----------------
extern "C" void kernel_launch(void* const* d_in, const int* in_sizes, int n_in,
                              void* d_out, int out_size) {
    (void)in_sizes; (void)n_in; (void)out_size;
    const float* x      = (const float*)d_in[0];
    const float* gn_w   = (const float*)d_in[1];
    const float* gn_b   = (const float*)d_in[2];
    const float* proj_w = (const float*)d_in[3];
    const float* proj_b = (const float*)d_in[4];
    float* out = (float*)d_out;

    float *t_, *zx_, *xbc_, *dt_, *acs_, *cb_, *st_, *pv_, *y_, *r_, *pr_, *stats_;
    cudaGetSymbolAddress((void**)&t_,    g_t);
    cudaGetSymbolAddress((void**)&zx_,   g_zx);
    cudaGetSymbolAddress((void**)&xbc_,  g_xbc);
    cudaGetSymbolAddress((void**)&dt_,   g_dt);
    cudaGetSymbolAddress((void**)&acs_,  g_acs);
    cudaGetSymbolAddress((void**)&cb_,   g_cb);
    cudaGetSymbolAddress((void**)&st_,   g_st);
    cudaGetSymbolAddress((void**)&pv_,   g_pv);
    cudaGetSymbolAddress((void**)&y_,    g_y);
    cudaGetSymbolAddress((void**)&r_,    g_r);
    cudaGetSymbolAddress((void**)&pr_,   g_pr);
    cudaGetSymbolAddress((void**)&stats_,g_stats);

    gn_stats_k<<<B_, 512>>>(x, stats_);
    gn_apply_k<<<dim3(L_ / 32, DM / 32, B_), dim3(32, 8)>>>(x, gn_w, gn_b, stats_, t_);

    for (int dir = 0; dir < 2; dir++) {
        const float* in_w    = (const float*)d_in[5 + dir * 8 + 0];
        const float* conv_w  = (const float*)d_in[5 + dir * 8 + 1];
        const float* conv_b  = (const float*)d_in[5 + dir * 8 + 2];
        const float* dt_bias = (const float*)d_in[5 + dir * 8 + 3];
        const float* A_log   = (const float*)d_in[5 + dir * 8 + 4];
        const float* Dh      = (const float*)d_in[5 + dir * 8 + 5];
        const float* norm_w  = (const float*)d_in[5 + dir * 8 + 6];
        const float* out_w   = (const float*)d_in[5 + dir * 8 + 7];

        // in-projection: (B*L,2320) = t @ in_w^T  (rows time-reversed for bwd)
        gemm_nt<<<dim3((DIP + 63) / 64, (B_ * L_) / 64, 1), 256>>>(
            t_, in_w, zx_, B_ * L_, DIP, DM, DM, DM, DIP, 0, 0, 0, dir ? L_ : 0);

        conv_silu_k<<<(B_ * L_ * CD + 255) / 256, 256>>>(zx_, conv_w, conv_b, xbc_);
        dt_scan_k<<<B_ * NH * NC, CH>>>(zx_, dt_bias, A_log, dt_, acs_);

        // CB = C @ B^T per (b,c)
        gemm_nt<<<dim3(CH / 64, CH / 64, B_ * NC), 256>>>(
            xbc_ + DI + DS, xbc_ + DI, cb_, CH, CH, DS, CD, CD, CH,
            (long long)CH * CD, (long long)CH * CD, (long long)CH * CH, 0);

        states_k<<<dim3(NH, NC, B_), 256>>>(xbc_, dt_, acs_, st_);
        chunkscan_k<<<(B_ * NH * HD * DS) / 256, 256>>>(st_, acs_, pv_);
        ssd_y_k<<<dim3(CH / 64, NH, B_ * NC), 256>>>(xbc_, dt_, acs_, cb_, pv_, Dh, y_);
        gate_rms_k<<<B_ * L_, 256>>>(y_, zx_, norm_w);

        // out-projection: (B*L,256) = y @ out_w^T
        gemm_nt<<<dim3(DM / 64, (B_ * L_) / 64, 1), 256>>>(
            y_, out_w, pr_, B_ * L_, DM, DI, DI, DI, DM, 0, 0, 0, 0);
        outproj_epi_k<<<(B_ * L_ * DM + 255) / 256, 256>>>(pr_, t_, r_, dir);
    }

    // final projection: (B*L,256) = r @ proj_w^T
    gemm_nt<<<dim3(DM / 64, (B_ * L_) / 64, 1), 256>>>(
        r_, proj_w, pr_, B_ * L_, DM, 2 * DM, 2 * DM, 2 * DM, DM, 0, 0, 0, 0);
    final_epi_k<<<(B_ * DM * L_ + 255) / 256, 256>>>(pr_, x, proj_b, out);
}

// round 2
// speedup vs baseline: 1.2576x; 1.2576x over previous
#include <cuda_runtime.h>
#include <cuda_bf16.h>
#include <math.h>

// ---------------- problem constants ----------------
static const int B_   = 2;
static const int L_   = 2048;
static const int DM   = 256;    // D_MODEL
static const int DS   = 128;    // D_STATE
static const int DI   = 1024;   // D_INNER
static const int NH   = 16;     // NHEADS
static const int HD   = 64;     // HEADDIM
static const int CD   = 1280;   // CONV_DIM
static const int DIP  = 2320;   // D_IN_PROJ
static const int CH   = 256;    // CHUNK
static const int NC   = 8;      // chunks per sequence
#define GN_EPS 1.1920928955078125e-07f
#define RMS_EPS 1e-5f

// ---------------- scratch (device globals, no allocs) ----------------
__device__ float g_t    [B_*L_*DM];
__device__ float g_zx   [B_*L_*DIP];
__device__ float g_xbc  [B_*L_*CD];
__device__ float g_dt   [B_*L_*NH];
__device__ float g_acs  [B_*NH*L_];
__device__ float g_cb   [B_*NC*CH*CH];
__device__ float g_st   [B_*NC*NH*HD*DS];
__device__ float g_pv   [B_*NC*NH*HD*DS];
__device__ float g_y    [B_*L_*DI];
__device__ float g_r    [B_*L_*2*DM];
__device__ float g_pr   [B_*L_*DM];
__device__ float g_stats[4];

__device__ __forceinline__ float siluf(float x) { return x / (1.f + expf(-x)); }
__device__ __forceinline__ float softplusf(float x) { return x > 20.f ? x : log1pf(expf(x)); }

// ---------------- GroupNorm stats ----------------
__global__ void gn_stats_k(const float* __restrict__ x, float* __restrict__ stats) {
    int b = blockIdx.x;
    const float* xb = x + (size_t)b * DM * L_;
    double s = 0.0, ss = 0.0;
    for (int i = threadIdx.x; i < DM * L_; i += blockDim.x) {
        double v = xb[i]; s += v; ss += v * v;
    }
    __shared__ double sh[512], sh2[512];
    sh[threadIdx.x] = s; sh2[threadIdx.x] = ss;
    __syncthreads();
    for (int o = 256; o > 0; o >>= 1) {
        if ((int)threadIdx.x < o) { sh[threadIdx.x] += sh[threadIdx.x + o]; sh2[threadIdx.x] += sh2[threadIdx.x + o]; }
        __syncthreads();
    }
    if (threadIdx.x == 0) {
        double n = (double)DM * L_;
        double mu = sh[0] / n;
        double var = sh2[0] / n - mu * mu;
        stats[b * 2 + 0] = (float)mu;
        stats[b * 2 + 1] = rsqrtf((float)var + GN_EPS);
    }
}

// ---------------- GroupNorm apply + transpose ----------------
__global__ void gn_apply_k(const float* __restrict__ x, const float* __restrict__ gw,
                           const float* __restrict__ gb, const float* __restrict__ stats,
                           float* __restrict__ t) {
    int b = blockIdx.z;
    __shared__ float tile[32][33];
    int l0 = blockIdx.x * 32, d0 = blockIdx.y * 32;
    float mu = stats[b * 2], rs = stats[b * 2 + 1];
#pragma unroll
    for (int r = 0; r < 4; r++) {
        int d = d0 + threadIdx.y + r * 8;
        tile[threadIdx.y + r * 8][threadIdx.x] = x[((size_t)b * DM + d) * L_ + l0 + threadIdx.x];
    }
    __syncthreads();
    int d = d0 + threadIdx.x;
    float w = gw[d], bb = gb[d];
#pragma unroll
    for (int r = 0; r < 4; r++) {
        int l = l0 + threadIdx.y + r * 8;
        t[((size_t)b * L_ + l) * DM + d] = (tile[threadIdx.x][threadIdx.y + r * 8] - mu) * rs * w + bb;
    }
}

// ---------------- high-throughput templated NT GEMM ----------------
// C[m,n] = sum_k A[m,k]*B[n,k]; optional time-reversal of A rows.
// Requires K % 16 == 0, lda/ldb multiples of 4, row pointers 16B aligned.
template<int BM, int BN, int TM, int TN>
__global__ void __launch_bounds__((BM/TM)*(BN/TN))
gemm_nt_t(const float* __restrict__ A, const float* __restrict__ Bp,
          float* __restrict__ C, int M, int N, int K,
          int lda, int ldb, int ldc,
          long long sA, long long sB, long long sC, int revL) {
    constexpr int BK = 16;
    constexpr int THREADS = (BM/TM)*(BN/TN);
    constexpr int LA = BM*BK/(THREADS*4);
    constexpr int LB = BN*BK/(THREADS*4);
    __shared__ float As[BK][BM+4];
    __shared__ float Bs[BK][BN+4];
    int z = blockIdx.z;
    A += z * sA; Bp += z * sB; C += z * sC;
    int m0 = blockIdx.y * BM, n0 = blockIdx.x * BN;
    int tid = threadIdx.x;
    int tx = tid % (BN/TN), ty = tid / (BN/TN);
    float acc[TM][TN] = {};
    float4 ra[LA], rb[LB];

    auto loadA = [&](int k0) {
#pragma unroll
        for (int i = 0; i < LA; i++) {
            int e = tid + i * THREADS;
            int mm = e / (BK/4);
            int kc = (e % (BK/4)) * 4;
            int gm = m0 + mm;
            float4 v = make_float4(0.f, 0.f, 0.f, 0.f);
            if (gm < M) {
                int row = gm;
                if (revL) { int bb = gm / revL; int ll = gm % revL; row = bb * revL + (revL - 1 - ll); }
                v = *reinterpret_cast<const float4*>(A + (long long)row * lda + k0 + kc);
            }
            ra[i] = v;
        }
    };
    auto loadB = [&](int k0) {
#pragma unroll
        for (int i = 0; i < LB; i++) {
            int e = tid + i * THREADS;
            int nn = e / (BK/4);
            int kc = (e % (BK/4)) * 4;
            int gn = n0 + nn;
            float4 v = make_float4(0.f, 0.f, 0.f, 0.f);
            if (gn < N) v = *reinterpret_cast<const float4*>(Bp + (long long)gn * ldb + k0 + kc);
            rb[i] = v;
        }
    };
    auto storeS = [&]() {
#pragma unroll
        for (int i = 0; i < LA; i++) {
            int e = tid + i * THREADS;
            int mm = e / (BK/4);
            int kc = (e % (BK/4)) * 4;
            As[kc][mm] = ra[i].x; As[kc+1][mm] = ra[i].y; As[kc+2][mm] = ra[i].z; As[kc+3][mm] = ra[i].w;
        }
#pragma unroll
        for (int i = 0; i < LB; i++) {
            int e = tid + i * THREADS;
            int nn = e / (BK/4);
            int kc = (e % (BK/4)) * 4;
            Bs[kc][nn] = rb[i].x; Bs[kc+1][nn] = rb[i].y; Bs[kc+2][nn] = rb[i].z; Bs[kc+3][nn] = rb[i].w;
        }
    };
    auto compute = [&]() {
#pragma unroll
        for (int kk = 0; kk < BK; kk++) {
            float av[TM], bv[TN];
#pragma unroll
            for (int i = 0; i < TM/4; i++)
                *reinterpret_cast<float4*>(av + 4*i) =
                    *reinterpret_cast<const float4*>(&As[kk][ty*TM + 4*i]);
#pragma unroll
            for (int j = 0; j < TN/4; j++)
                *reinterpret_cast<float4*>(bv + 4*j) =
                    *reinterpret_cast<const float4*>(&Bs[kk][tx*TN + 4*j]);
#pragma unroll
            for (int i = 0; i < TM; i++)
#pragma unroll
                for (int j = 0; j < TN; j++) acc[i][j] += av[i] * bv[j];
        }
    };

    loadA(0); loadB(0);
    storeS();
    __syncthreads();
    for (int k0 = BK; k0 < K; k0 += BK) {
        loadA(k0); loadB(k0);   // prefetch next tile into registers
        compute();              // compute on current smem tile
        __syncthreads();
        storeS();
        __syncthreads();
    }
    compute();

#pragma unroll
    for (int i = 0; i < TM; i++) {
        int gm = m0 + ty*TM + i;
        if (gm < M) {
#pragma unroll
            for (int j = 0; j < TN; j++) {
                int gn = n0 + tx*TN + j;
                if (gn < N) C[(long long)gm * ldc + gn] = acc[i][j];
            }
        }
    }
}

// ---------------- depthwise conv (k=4, causal) + SiLU ----------------
__global__ void conv_silu_k(const float* __restrict__ zx, const float* __restrict__ cw,
                            const float* __restrict__ cb, float* __restrict__ xbc) {
    int idx = blockIdx.x * blockDim.x + threadIdx.x;
    if (idx >= B_ * L_ * CD) return;
    int ch = idx % CD;
    int l  = (idx / CD) % L_;
    int b  = idx / (CD * L_);
    float acc = cb[ch];
#pragma unroll
    for (int k = 0; k < 4; k++) {
        int lp = l - 3 + k;
        if (lp >= 0) acc += cw[ch * 4 + k] * zx[(size_t)(b * L_ + lp) * DIP + DI + ch];
    }
    xbc[idx] = siluf(acc);
}

// ---------------- dt = softplus(raw + bias); A cumsum per chunk ----------------
__global__ void dt_scan_k(const float* __restrict__ zx, const float* __restrict__ dt_bias,
                          const float* __restrict__ A_log, float* __restrict__ dt,
                          float* __restrict__ acs) {
    int bi = blockIdx.x;
    int c = bi % NC, h = (bi / NC) % NH, b = bi / (NC * NH);
    int l = threadIdx.x;
    int gl = c * CH + l;
    int row = b * L_ + gl;
    float v = zx[(size_t)row * DIP + (DIP - NH) + h] + dt_bias[h];
    float dtv = softplusf(v);
    dt[row * NH + h] = dtv;
    float a = -expf(A_log[h]) * dtv;
    __shared__ float sb[CH];
    sb[l] = a;
    __syncthreads();
    for (int off = 1; off < CH; off <<= 1) {
        float tv = (l >= off) ? sb[l - off] : 0.f;
        __syncthreads();
        sb[l] += tv;
        __syncthreads();
    }
    acs[(b * NH + h) * L_ + gl] = sb[l];
}

// ---------------- per-chunk end state ----------------
__global__ void states_k(const float* __restrict__ xbc, const float* __restrict__ dt,
                         const float* __restrict__ acs, float* __restrict__ st) {
    int h = blockIdx.x, c = blockIdx.y, b = blockIdx.z;
    int tid = threadIdx.x;
    __shared__ float Xs[32][65];
    __shared__ float Bs[32][129];
    int acsbase = (b * NH + h) * L_ + c * CH;
    float csLast = acs[acsbase + CH - 1];
    float accv[32];
#pragma unroll
    for (int j = 0; j < 32; j++) accv[j] = 0.f;
    int p = tid & 63, ng = tid >> 6;
    for (int s0 = 0; s0 < CH; s0 += 32) {
#pragma unroll
        for (int i = 0; i < 8; i++) {
            int e = tid + i * 256;
            int pp = e & 63, ss = e >> 6;
            int row = b * L_ + c * CH + s0 + ss;
            float w = dt[row * NH + h] * expf(csLast - acs[acsbase + s0 + ss]);
            Xs[ss][pp] = xbc[(size_t)row * CD + h * HD + pp] * w;
        }
#pragma unroll
        for (int i = 0; i < 16; i++) {
            int e = tid + i * 256;
            int nn = e & 127, ss = e >> 7;
            int row = b * L_ + c * CH + s0 + ss;
            Bs[ss][nn] = xbc[(size_t)row * CD + DI + nn];
        }
        __syncthreads();
#pragma unroll
        for (int ss = 0; ss < 32; ss++) {
            float xv = Xs[ss][p];
#pragma unroll
            for (int j = 0; j < 32; j++) accv[j] += xv * Bs[ss][ng * 32 + j];
        }
        __syncthreads();
    }
    size_t base = ((size_t)((b * NC + c) * NH + h) * HD + p) * DS + ng * 32;
#pragma unroll
    for (int j = 0; j < 32; j++) st[base + j] = accv[j];
}

// ---------------- inter-chunk recurrence ----------------
__global__ void chunkscan_k(const float* __restrict__ st, const float* __restrict__ acs,
                            float* __restrict__ pv) {
    int idx = blockIdx.x * blockDim.x + threadIdx.x;
    int n = idx & (DS - 1);
    int p = (idx >> 7) & (HD - 1);
    int h = (idx >> 13) & (NH - 1);
    int b = idx >> 17;
    float S = 0.f;
    for (int c = 0; c < NC; c++) {
        size_t off = ((size_t)((b * NC + c) * NH + h) * HD + p) * DS + n;
        pv[off] = S;
        float at = acs[(b * NH + h) * L_ + c * CH + CH - 1];
        S = S * expf(at) + st[off];
    }
}

// ---------------- Y = diag + off-diag + D skip ----------------
__global__ void ssd_y_k(const float* __restrict__ xbc, const float* __restrict__ dt,
                        const float* __restrict__ acs, const float* __restrict__ cb,
                        const float* __restrict__ pv, const float* __restrict__ Dh,
                        float* __restrict__ y) {
    int lt = blockIdx.x, h = blockIdx.y, bc = blockIdx.z;
    int c = bc % NC, b = bc / NC;
    int tid = threadIdx.x;
    int tx = tid & 15, ty = tid >> 4;
    __shared__ float Ws[64][33];
    __shared__ float Xs[32][65];
    __shared__ float csl[64], css[32];
    int l0 = lt * 64;
    int acsbase = (b * NH + h) * L_ + c * CH;
    if (tid < 64) csl[tid] = acs[acsbase + l0 + tid];
    const float* cbb = cb + (size_t)(b * NC + c) * CH * CH;
    float acc[4][4] = {};
    float acc2[4][4] = {};
    int nst = 2 * lt + 2;
    for (int st = 0; st < nst; st++) {
        int s0 = st * 32;
        __syncthreads();
        if (tid < 32) css[tid] = acs[acsbase + s0 + tid];
#pragma unroll
        for (int i = 0; i < 8; i++) {
            int e = tid + i * 256;
            int pp = e & 63, ss = e >> 6;
            int row = b * L_ + c * CH + s0 + ss;
            Xs[ss][pp] = xbc[(size_t)row * CD + h * HD + pp] * dt[row * NH + h];
        }
        __syncthreads();
#pragma unroll
        for (int i = 0; i < 8; i++) {
            int e = tid + i * 256;
            int j = e & 31, ii = e >> 5;
            float w = 0.f;
            if (s0 + j <= l0 + ii) w = expf(csl[ii] - css[j]) * cbb[(l0 + ii) * CH + s0 + j];
            Ws[ii][j] = w;
        }
        __syncthreads();
#pragma unroll
        for (int kk = 0; kk < 32; kk++) {
            float av[4], bv[4];
#pragma unroll
            for (int i = 0; i < 4; i++) av[i] = Ws[ty * 4 + i][kk];
#pragma unroll
            for (int j = 0; j < 4; j++) bv[j] = Xs[kk][tx * 4 + j];
#pragma unroll
            for (int i = 0; i < 4; i++)
#pragma unroll
                for (int j = 0; j < 4; j++) acc[i][j] += av[i] * bv[j];
        }
    }
    const float* pvb = pv + (size_t)((b * NC + c) * NH + h) * HD * DS;
    for (int nt = 0; nt < 4; nt++) {
        int n0 = nt * 32;
        __syncthreads();
#pragma unroll
        for (int i = 0; i < 8; i++) {
            int e = tid + i * 256;
            int j = e & 31, ii = e >> 5;
            int row = b * L_ + c * CH + l0 + ii;
            Ws[ii][j] = xbc[(size_t)row * CD + DI + DS + n0 + j];
        }
#pragma unroll
        for (int i = 0; i < 8; i++) {
            int e = tid + i * 256;
            int j = e & 31, pp = e >> 5;
            Xs[j][pp] = pvb[pp * DS + n0 + j];
        }
        __syncthreads();
#pragma unroll
        for (int kk = 0; kk < 32; kk++) {
            float av[4], bv[4];
#pragma unroll
            for (int i = 0; i < 4; i++) av[i] = Ws[ty * 4 + i][kk];
#pragma unroll
            for (int j = 0; j < 4; j++) bv[j] = Xs[kk][tx * 4 + j];
#pragma unroll
            for (int i = 0; i < 4; i++)
#pragma unroll
                for (int j = 0; j < 4; j++) acc2[i][j] += av[i] * bv[j];
        }
    }
    float dh = Dh[h];
#pragma unroll
    for (int i = 0; i < 4; i++) {
        int ll = l0 + ty * 4 + i;
        int row = b * L_ + c * CH + ll;
        float sd = expf(csl[ty * 4 + i]);
#pragma unroll
        for (int j = 0; j < 4; j++) {
            int pp = tx * 4 + j;
            float xraw = xbc[(size_t)row * CD + h * HD + pp];
            y[(size_t)row * DI + h * HD + pp] = acc[i][j] + sd * acc2[i][j] + xraw * dh;
        }
    }
}

// ---------------- gating + RMSNorm ----------------
__global__ void gate_rms_k(float* __restrict__ y, const float* __restrict__ zx,
                           const float* __restrict__ nw) {
    int row = blockIdx.x;
    int tid = threadIdx.x;
    float v[4];
    float ss = 0.f;
#pragma unroll
    for (int i = 0; i < 4; i++) {
        int d = i * 256 + tid;
        float z = zx[(size_t)row * DIP + d];
        float yy = y[(size_t)row * DI + d] * siluf(z);
        v[i] = yy;
        ss += yy * yy;
    }
    __shared__ float sh[256];
    sh[tid] = ss;
    __syncthreads();
    for (int o = 128; o > 0; o >>= 1) {
        if (tid < o) sh[tid] += sh[tid + o];
        __syncthreads();
    }
    float scale = rsqrtf(sh[0] / DI + RMS_EPS);
#pragma unroll
    for (int i = 0; i < 4; i++) {
        int d = i * 256 + tid;
        y[(size_t)row * DI + d] = v[i] * scale * nw[d];
    }
}

// ---------------- out-proj epilogue ----------------
__global__ void outproj_epi_k(const float* __restrict__ pr, const float* __restrict__ t,
                              float* __restrict__ r, int dir) {
    int idx = blockIdx.x * blockDim.x + threadIdx.x;
    if (idx >= B_ * L_ * DM) return;
    int d = idx % DM;
    int l = (idx / DM) % L_;
    int b = idx / (DM * L_);
    int ltm = dir ? (L_ - 1 - l) : l;
    r[(size_t)(b * L_ + ltm) * (2 * DM) + dir * DM + d] = pr[idx] + t[(size_t)(b * L_ + ltm) * DM + d];
}

// ---------------- final epilogue ----------------
__global__ void final_epi_k(const float* __restrict__ pr, const float* __restrict__ x,
                            const float* __restrict__ pb, float* __restrict__ out) {
    int idx = blockIdx.x * blockDim.x + threadIdx.x;
    if (idx >= B_ * DM * L_) return;
    int l = idx % L_;
    int d = (idx / L_) % DM;
    int b = idx / (L_ * DM);
    out[idx] = x[idx] + pr[(size_t)(b * L_ + l) * DM + d] + pb[d];
}

// ---------------- launch ----------------
extern "C" void kernel_launch(void* const* d_in, const int* in_sizes, int n_in,
                              void* d_out, int out_size) {
    (void)in_sizes; (void)n_in; (void)out_size;
    const float* x      = (const float*)d_in[0];
    const float* gn_w   = (const float*)d_in[1];
    const float* gn_b   = (const float*)d_in[2];
    const float* proj_w = (const float*)d_in[3];
    const float* proj_b = (const float*)d_in[4];
    float* out = (float*)d_out;

    float *t_, *zx_, *xbc_, *dt_, *acs_, *cb_, *st_, *pv_, *y_, *r_, *pr_, *stats_;
    cudaGetSymbolAddress((void**)&t_,    g_t);
    cudaGetSymbolAddress((void**)&zx_,   g_zx);
    cudaGetSymbolAddress((void**)&xbc_,  g_xbc);
    cudaGetSymbolAddress((void**)&dt_,   g_dt);
    cudaGetSymbolAddress((void**)&acs_,  g_acs);
    cudaGetSymbolAddress((void**)&cb_,   g_cb);
    cudaGetSymbolAddress((void**)&st_,   g_st);
    cudaGetSymbolAddress((void**)&pv_,   g_pv);
    cudaGetSymbolAddress((void**)&y_,    g_y);
    cudaGetSymbolAddress((void**)&r_,    g_r);
    cudaGetSymbolAddress((void**)&pr_,   g_pr);
    cudaGetSymbolAddress((void**)&stats_,g_stats);

    gn_stats_k<<<B_, 512>>>(x, stats_);
    gn_apply_k<<<dim3(L_ / 32, DM / 32, B_), dim3(32, 8)>>>(x, gn_w, gn_b, stats_, t_);

    for (int dir = 0; dir < 2; dir++) {
        const float* in_w    = (const float*)d_in[5 + dir * 8 + 0];
        const float* conv_w  = (const float*)d_in[5 + dir * 8 + 1];
        const float* conv_b  = (const float*)d_in[5 + dir * 8 + 2];
        const float* dt_bias = (const float*)d_in[5 + dir * 8 + 3];
        const float* A_log   = (const float*)d_in[5 + dir * 8 + 4];
        const float* Dh      = (const float*)d_in[5 + dir * 8 + 5];
        const float* norm_w  = (const float*)d_in[5 + dir * 8 + 6];
        const float* out_w   = (const float*)d_in[5 + dir * 8 + 7];

        // in-projection: (B*L,2320) = t @ in_w^T  (rows time-reversed for bwd)
        gemm_nt_t<128,128,8,8><<<dim3((DIP + 127) / 128, (B_ * L_) / 128, 1), 256>>>(
            t_, in_w, zx_, B_ * L_, DIP, DM, DM, DM, DIP, 0, 0, 0, dir ? L_ : 0);

        conv_silu_k<<<(B_ * L_ * CD + 255) / 256, 256>>>(zx_, conv_w, conv_b, xbc_);
        dt_scan_k<<<B_ * NH * NC, CH>>>(zx_, dt_bias, A_log, dt_, acs_);

        // CB = C @ B^T per (b,c)
        gemm_nt_t<64,64,8,4><<<dim3(CH / 64, CH / 64, B_ * NC), 128>>>(
            xbc_ + DI + DS, xbc_ + DI, cb_, CH, CH, DS, CD, CD, CH,
            (long long)CH * CD, (long long)CH * CD, (long long)CH * CH, 0);

        states_k<<<dim3(NH, NC, B_), 256>>>(xbc_, dt_, acs_, st_);
        chunkscan_k<<<(B_ * NH * HD * DS) / 256, 256>>>(st_, acs_, pv_);
        ssd_y_k<<<dim3(CH / 64, NH, B_ * NC), 256>>>(xbc_, dt_, acs_, cb_, pv_, Dh, y_);
        gate_rms_k<<<B_ * L_, 256>>>(y_, zx_, norm_w);

        // out-projection: (B*L,256) = y @ out_w^T
        gemm_nt_t<64,64,8,4><<<dim3(DM / 64, (B_ * L_) / 64, 1), 128>>>(
            y_, out_w, pr_, B_ * L_, DM, DI, DI, DI, DM, 0, 0, 0, 0);
        outproj_epi_k<<<(B_ * L_ * DM + 255) / 256, 256>>>(pr_, t_, r_, dir);
    }

    // final projection: (B*L,256) = r @ proj_w^T
    gemm_nt_t<64,64,8,4><<<dim3(DM / 64, (B_ * L_) / 64, 1), 128>>>(
        r_, proj_w, pr_, B_ * L_, DM, 2 * DM, 2 * DM, 2 * DM, DM, 0, 0, 0, 0);
    final_epi_k<<<(B_ * DM * L_ + 255) / 256, 256>>>(pr_, x, proj_b, out);
}

// round 3
// speedup vs baseline: 1.5012x; 1.1937x over previous
#include <cuda_runtime.h>
#include <cuda_bf16.h>
#include <math.h>
#include <stdint.h>

// ---------------- problem constants ----------------
static const int B_   = 2;
static const int L_   = 2048;
static const int DM   = 256;
static const int DS   = 128;
static const int DI   = 1024;
static const int NH   = 16;
static const int HD   = 64;
static const int CD   = 1280;
static const int DIP  = 2320;
static const int CH   = 256;
static const int NC   = 8;
#define GN_EPS 1.1920928955078125e-07f
#define RMS_EPS 1e-5f

// ---------------- scratch ----------------
__device__ float g_t    [B_*L_*DM];
__device__ float g_zx   [B_*L_*DIP];
__device__ float g_xbc  [B_*L_*CD];
__device__ float g_dt   [B_*L_*NH];
__device__ float g_acs  [B_*NH*L_];
__device__ float g_cb   [B_*NC*CH*CH];
__device__ float g_st   [B_*NC*NH*HD*DS];
__device__ float g_pv   [B_*NC*NH*HD*DS];
__device__ float g_y    [B_*L_*DI];
__device__ float g_r    [B_*L_*2*DM];
__device__ float g_pr   [B_*L_*DM];
__device__ float g_stats[4];

__device__ __forceinline__ float siluf(float x) { return x / (1.f + expf(-x)); }
__device__ __forceinline__ float softplusf(float x) { return x > 20.f ? x : log1pf(expf(x)); }
__device__ __forceinline__ uint32_t f2tf32(float x) {
    uint32_t r; asm("cvt.rna.tf32.f32 %0, %1;" : "=r"(r) : "f"(x)); return r;
}

// ---------------- GroupNorm stats ----------------
__global__ void gn_stats_k(const float* __restrict__ x, float* __restrict__ stats) {
    int b = blockIdx.x;
    const float* xb = x + (size_t)b * DM * L_;
    double s = 0.0, ss = 0.0;
    for (int i = threadIdx.x; i < DM * L_; i += blockDim.x) {
        double v = xb[i]; s += v; ss += v * v;
    }
    __shared__ double sh[512], sh2[512];
    sh[threadIdx.x] = s; sh2[threadIdx.x] = ss;
    __syncthreads();
    for (int o = 256; o > 0; o >>= 1) {
        if ((int)threadIdx.x < o) { sh[threadIdx.x] += sh[threadIdx.x + o]; sh2[threadIdx.x] += sh2[threadIdx.x + o]; }
        __syncthreads();
    }
    if (threadIdx.x == 0) {
        double n = (double)DM * L_;
        double mu = sh[0] / n;
        double var = sh2[0] / n - mu * mu;
        stats[b * 2 + 0] = (float)mu;
        stats[b * 2 + 1] = rsqrtf((float)var + GN_EPS);
    }
}

// ---------------- GroupNorm apply + transpose ----------------
__global__ void gn_apply_k(const float* __restrict__ x, const float* __restrict__ gw,
                           const float* __restrict__ gb, const float* __restrict__ stats,
                           float* __restrict__ t) {
    int b = blockIdx.z;
    __shared__ float tile[32][33];
    int l0 = blockIdx.x * 32, d0 = blockIdx.y * 32;
    float mu = stats[b * 2], rs = stats[b * 2 + 1];
#pragma unroll
    for (int r = 0; r < 4; r++) {
        int d = d0 + threadIdx.y + r * 8;
        tile[threadIdx.y + r * 8][threadIdx.x] = x[((size_t)b * DM + d) * L_ + l0 + threadIdx.x];
    }
    __syncthreads();
    int d = d0 + threadIdx.x;
    float w = gw[d], bb = gb[d];
#pragma unroll
    for (int r = 0; r < 4; r++) {
        int l = l0 + threadIdx.y + r * 8;
        t[((size_t)b * L_ + l) * DM + d] = (tile[threadIdx.x][threadIdx.y + r * 8] - mu) * rs * w + bb;
    }
}

// ---------------- TF32 tensor-core NT GEMM ----------------
// C[m,n] = sum_k A[m,k]*B[n,k] via mma.sync.m16n8k8.tf32. Requires K%32==0.
// 256 threads, 8 warps as 2(M)x4(N). revL: time-reverse A rows per sequence.
template<int BM, int BN>
__global__ void __launch_bounds__(256)
gemm_tf32(const float* __restrict__ A, const float* __restrict__ Bp,
          float* __restrict__ C, int M, int N, int K,
          int lda, int ldb, int ldc,
          long long sA, long long sB, long long sC, int revL) {
    constexpr int BK = 32;
    constexpr int T  = 256;
    constexpr int LA = BM * BK / (T * 4);
    constexpr int LB = BN * BK / (T * 4);
    constexpr int MF = BM / 32;   // 16-row frags per warp (2 warps in M)
    constexpr int NF = BN / 32;   // 8-col frags per warp (4 warps in N)
    __shared__ float As[BM][BK + 4];
    __shared__ float Bs[BN][BK + 4];
    int z = blockIdx.z;
    A += z * sA; Bp += z * sB; C += z * sC;
    int m0 = blockIdx.y * BM, n0 = blockIdx.x * BN;
    int tid = threadIdx.x;
    int warp = tid >> 5, lane = tid & 31;
    int wm = warp >> 2, wn = warp & 3;
    int group = lane >> 2, tig = lane & 3;
    float acc[MF][NF][4] = {};
    float4 ra[LA], rb[LB];

    auto loadA = [&](int k0) {
#pragma unroll
        for (int i = 0; i < LA; i++) {
            int e = tid + i * T;
            int mm = e / (BK / 4);
            int kc = (e % (BK / 4)) * 4;
            int gm = m0 + mm;
            float4 v = make_float4(0.f, 0.f, 0.f, 0.f);
            if (gm < M) {
                int row = gm;
                if (revL) { int bb = gm / revL; int ll = gm % revL; row = bb * revL + (revL - 1 - ll); }
                v = *reinterpret_cast<const float4*>(A + (long long)row * lda + k0 + kc);
            }
            ra[i] = v;
        }
    };
    auto loadB = [&](int k0) {
#pragma unroll
        for (int i = 0; i < LB; i++) {
            int e = tid + i * T;
            int nn = e / (BK / 4);
            int kc = (e % (BK / 4)) * 4;
            int gn = n0 + nn;
            float4 v = make_float4(0.f, 0.f, 0.f, 0.f);
            if (gn < N) v = *reinterpret_cast<const float4*>(Bp + (long long)gn * ldb + k0 + kc);
            rb[i] = v;
        }
    };
    auto storeS = [&]() {
#pragma unroll
        for (int i = 0; i < LA; i++) {
            int e = tid + i * T;
            int mm = e / (BK / 4);
            int kc = (e % (BK / 4)) * 4;
            As[mm][kc]   = __uint_as_float(f2tf32(ra[i].x));
            As[mm][kc+1] = __uint_as_float(f2tf32(ra[i].y));
            As[mm][kc+2] = __uint_as_float(f2tf32(ra[i].z));
            As[mm][kc+3] = __uint_as_float(f2tf32(ra[i].w));
        }
#pragma unroll
        for (int i = 0; i < LB; i++) {
            int e = tid + i * T;
            int nn = e / (BK / 4);
            int kc = (e % (BK / 4)) * 4;
            Bs[nn][kc]   = __uint_as_float(f2tf32(rb[i].x));
            Bs[nn][kc+1] = __uint_as_float(f2tf32(rb[i].y));
            Bs[nn][kc+2] = __uint_as_float(f2tf32(rb[i].z));
            Bs[nn][kc+3] = __uint_as_float(f2tf32(rb[i].w));
        }
    };
    auto compute = [&]() {
#pragma unroll
        for (int ks = 0; ks < BK / 8; ks++) {
            uint32_t af[MF][4], bf[NF][2];
#pragma unroll
            for (int mf = 0; mf < MF; mf++) {
                int rm = wm * (MF * 16) + mf * 16 + group;
                af[mf][0] = __float_as_uint(As[rm    ][ks * 8 + tig]);
                af[mf][1] = __float_as_uint(As[rm + 8][ks * 8 + tig]);
                af[mf][2] = __float_as_uint(As[rm    ][ks * 8 + tig + 4]);
                af[mf][3] = __float_as_uint(As[rm + 8][ks * 8 + tig + 4]);
            }
#pragma unroll
            for (int nf = 0; nf < NF; nf++) {
                int rn = wn * (NF * 8) + nf * 8 + group;
                bf[nf][0] = __float_as_uint(Bs[rn][ks * 8 + tig]);
                bf[nf][1] = __float_as_uint(Bs[rn][ks * 8 + tig + 4]);
            }
#pragma unroll
            for (int mf = 0; mf < MF; mf++)
#pragma unroll
                for (int nf = 0; nf < NF; nf++) {
                    asm volatile(
                        "mma.sync.aligned.m16n8k8.row.col.f32.tf32.tf32.f32 "
                        "{%0,%1,%2,%3},{%4,%5,%6,%7},{%8,%9},{%0,%1,%2,%3};"
                        : "+f"(acc[mf][nf][0]), "+f"(acc[mf][nf][1]),
                          "+f"(acc[mf][nf][2]), "+f"(acc[mf][nf][3])
                        : "r"(af[mf][0]), "r"(af[mf][1]), "r"(af[mf][2]), "r"(af[mf][3]),
                          "r"(bf[nf][0]), "r"(bf[nf][1]));
                }
        }
    };

    loadA(0); loadB(0);
    storeS();
    __syncthreads();
    for (int k0 = BK; k0 < K; k0 += BK) {
        loadA(k0); loadB(k0);
        compute();
        __syncthreads();
        storeS();
        __syncthreads();
    }
    compute();

#pragma unroll
    for (int mf = 0; mf < MF; mf++) {
#pragma unroll
        for (int nf = 0; nf < NF; nf++) {
            int gm = m0 + wm * (MF * 16) + mf * 16 + group;
            int gn = n0 + wn * (NF * 8) + nf * 8 + 2 * tig;
            if (gn < N) {
                if (gm < M)
                    *reinterpret_cast<float2*>(C + (long long)gm * ldc + gn) =
                        make_float2(acc[mf][nf][0], acc[mf][nf][1]);
                if (gm + 8 < M)
                    *reinterpret_cast<float2*>(C + (long long)(gm + 8) * ldc + gn) =
                        make_float2(acc[mf][nf][2], acc[mf][nf][3]);
            }
        }
    }
}

// ---------------- depthwise conv (k=4, causal) + SiLU ----------------
__global__ void conv_silu_k(const float* __restrict__ zx, const float* __restrict__ cw,
                            const float* __restrict__ cb, float* __restrict__ xbc) {
    int idx = blockIdx.x * blockDim.x + threadIdx.x;
    if (idx >= B_ * L_ * CD) return;
    int ch = idx % CD;
    int l  = (idx / CD) % L_;
    int b  = idx / (CD * L_);
    float acc = cb[ch];
#pragma unroll
    for (int k = 0; k < 4; k++) {
        int lp = l - 3 + k;
        if (lp >= 0) acc += cw[ch * 4 + k] * zx[(size_t)(b * L_ + lp) * DIP + DI + ch];
    }
    xbc[idx] = siluf(acc);
}

// ---------------- dt softplus + per-chunk cumsum ----------------
__global__ void dt_scan_k(const float* __restrict__ zx, const float* __restrict__ dt_bias,
                          const float* __restrict__ A_log, float* __restrict__ dt,
                          float* __restrict__ acs) {
    int bi = blockIdx.x;
    int c = bi % NC, h = (bi / NC) % NH, b = bi / (NC * NH);
    int l = threadIdx.x;
    int gl = c * CH + l;
    int row = b * L_ + gl;
    float v = zx[(size_t)row * DIP + (DIP - NH) + h] + dt_bias[h];
    float dtv = softplusf(v);
    dt[row * NH + h] = dtv;
    float a = -expf(A_log[h]) * dtv;
    __shared__ float sb[CH];
    sb[l] = a;
    __syncthreads();
    for (int off = 1; off < CH; off <<= 1) {
        float tv = (l >= off) ? sb[l - off] : 0.f;
        __syncthreads();
        sb[l] += tv;
        __syncthreads();
    }
    acs[(b * NH + h) * L_ + gl] = sb[l];
}

// ---------------- per-chunk end state ----------------
__global__ void states_k(const float* __restrict__ xbc, const float* __restrict__ dt,
                         const float* __restrict__ acs, float* __restrict__ st) {
    int h = blockIdx.x, c = blockIdx.y, b = blockIdx.z;
    int tid = threadIdx.x;
    __shared__ float Xs[32][65];
    __shared__ float Bs[32][129];
    int acsbase = (b * NH + h) * L_ + c * CH;
    float csLast = acs[acsbase + CH - 1];
    float accv[32];
#pragma unroll
    for (int j = 0; j < 32; j++) accv[j] = 0.f;
    int p = tid & 63, ng = tid >> 6;
    for (int s0 = 0; s0 < CH; s0 += 32) {
#pragma unroll
        for (int i = 0; i < 8; i++) {
            int e = tid + i * 256;
            int pp = e & 63, ss = e >> 6;
            int row = b * L_ + c * CH + s0 + ss;
            float w = dt[row * NH + h] * expf(csLast - acs[acsbase + s0 + ss]);
            Xs[ss][pp] = xbc[(size_t)row * CD + h * HD + pp] * w;
        }
#pragma unroll
        for (int i = 0; i < 16; i++) {
            int e = tid + i * 256;
            int nn = e & 127, ss = e >> 7;
            int row = b * L_ + c * CH + s0 + ss;
            Bs[ss][nn] = xbc[(size_t)row * CD + DI + nn];
        }
        __syncthreads();
#pragma unroll
        for (int ss = 0; ss < 32; ss++) {
            float xv = Xs[ss][p];
#pragma unroll
            for (int j = 0; j < 32; j++) accv[j] += xv * Bs[ss][ng * 32 + j];
        }
        __syncthreads();
    }
    size_t base = ((size_t)((b * NC + c) * NH + h) * HD + p) * DS + ng * 32;
#pragma unroll
    for (int j = 0; j < 32; j++) st[base + j] = accv[j];
}

// ---------------- inter-chunk recurrence ----------------
__global__ void chunkscan_k(const float* __restrict__ st, const float* __restrict__ acs,
                            float* __restrict__ pv) {
    int idx = blockIdx.x * blockDim.x + threadIdx.x;
    int n = idx & (DS - 1);
    int p = (idx >> 7) & (HD - 1);
    int h = (idx >> 13) & (NH - 1);
    int b = idx >> 17;
    float S = 0.f;
    for (int c = 0; c < NC; c++) {
        size_t off = ((size_t)((b * NC + c) * NH + h) * HD + p) * DS + n;
        pv[off] = S;
        float at = acs[(b * NH + h) * L_ + c * CH + CH - 1];
        S = S * expf(at) + st[off];
    }
}

// ---------------- Y = diag + off-diag + D skip ----------------
__global__ void ssd_y_k(const float* __restrict__ xbc, const float* __restrict__ dt,
                        const float* __restrict__ acs, const float* __restrict__ cb,
                        const float* __restrict__ pv, const float* __restrict__ Dh,
                        float* __restrict__ y) {
    int lt = blockIdx.x, h = blockIdx.y, bc = blockIdx.z;
    int c = bc % NC, b = bc / NC;
    int tid = threadIdx.x;
    int tx = tid & 15, ty = tid >> 4;
    __shared__ float Ws[64][33];
    __shared__ float Xs[32][65];
    __shared__ float csl[64], css[32];
    int l0 = lt * 64;
    int acsbase = (b * NH + h) * L_ + c * CH;
    if (tid < 64) csl[tid] = acs[acsbase + l0 + tid];
    const float* cbb = cb + (size_t)(b * NC + c) * CH * CH;
    float acc[4][4] = {};
    float acc2[4][4] = {};
    int nst = 2 * lt + 2;
    for (int st = 0; st < nst; st++) {
        int s0 = st * 32;
        __syncthreads();
        if (tid < 32) css[tid] = acs[acsbase + s0 + tid];
#pragma unroll
        for (int i = 0; i < 8; i++) {
            int e = tid + i * 256;
            int pp = e & 63, ss = e >> 6;
            int row = b * L_ + c * CH + s0 + ss;
            Xs[ss][pp] = xbc[(size_t)row * CD + h * HD + pp] * dt[row * NH + h];
        }
        __syncthreads();
#pragma unroll
        for (int i = 0; i < 8; i++) {
            int e = tid + i * 256;
            int j = e & 31, ii = e >> 5;
            float w = 0.f;
            if (s0 + j <= l0 + ii) w = expf(csl[ii] - css[j]) * cbb[(l0 + ii) * CH + s0 + j];
            Ws[ii][j] = w;
        }
        __syncthreads();
#pragma unroll
        for (int kk = 0; kk < 32; kk++) {
            float av[4], bv[4];
#pragma unroll
            for (int i = 0; i < 4; i++) av[i] = Ws[ty * 4 + i][kk];
#pragma unroll
            for (int j = 0; j < 4; j++) bv[j] = Xs[kk][tx * 4 + j];
#pragma unroll
            for (int i = 0; i < 4; i++)
#pragma unroll
                for (int j = 0; j < 4; j++) acc[i][j] += av[i] * bv[j];
        }
    }
    const float* pvb = pv + (size_t)((b * NC + c) * NH + h) * HD * DS;
    for (int nt = 0; nt < 4; nt++) {
        int n0 = nt * 32;
        __syncthreads();
#pragma unroll
        for (int i = 0; i < 8; i++) {
            int e = tid + i * 256;
            int j = e & 31, ii = e >> 5;
            int row = b * L_ + c * CH + l0 + ii;
            Ws[ii][j] = xbc[(size_t)row * CD + DI + DS + n0 + j];
        }
#pragma unroll
        for (int i = 0; i < 8; i++) {
            int e = tid + i * 256;
            int j = e & 31, pp = e >> 5;
            Xs[j][pp] = pvb[pp * DS + n0 + j];
        }
        __syncthreads();
#pragma unroll
        for (int kk = 0; kk < 32; kk++) {
            float av[4], bv[4];
#pragma unroll
            for (int i = 0; i < 4; i++) av[i] = Ws[ty * 4 + i][kk];
#pragma unroll
            for (int j = 0; j < 4; j++) bv[j] = Xs[kk][tx * 4 + j];
#pragma unroll
            for (int i = 0; i < 4; i++)
#pragma unroll
                for (int j = 0; j < 4; j++) acc2[i][j] += av[i] * bv[j];
        }
    }
    float dh = Dh[h];
#pragma unroll
    for (int i = 0; i < 4; i++) {
        int ll = l0 + ty * 4 + i;
        int row = b * L_ + c * CH + ll;
        float sd = expf(csl[ty * 4 + i]);
#pragma unroll
        for (int j = 0; j < 4; j++) {
            int pp = tx * 4 + j;
            float xraw = xbc[(size_t)row * CD + h * HD + pp];
            y[(size_t)row * DI + h * HD + pp] = acc[i][j] + sd * acc2[i][j] + xraw * dh;
        }
    }
}

// ---------------- gating + RMSNorm ----------------
__global__ void gate_rms_k(float* __restrict__ y, const float* __restrict__ zx,
                           const float* __restrict__ nw) {
    int row = blockIdx.x;
    int tid = threadIdx.x;
    float v[4];
    float ss = 0.f;
#pragma unroll
    for (int i = 0; i < 4; i++) {
        int d = i * 256 + tid;
        float z = zx[(size_t)row * DIP + d];
        float yy = y[(size_t)row * DI + d] * siluf(z);
        v[i] = yy;
        ss += yy * yy;
    }
    __shared__ float sh[256];
    sh[tid] = ss;
    __syncthreads();
    for (int o = 128; o > 0; o >>= 1) {
        if (tid < o) sh[tid] += sh[tid + o];
        __syncthreads();
    }
    float scale = rsqrtf(sh[0] / DI + RMS_EPS);
#pragma unroll
    for (int i = 0; i < 4; i++) {
        int d = i * 256 + tid;
        y[(size_t)row * DI + d] = v[i] * scale * nw[d];
    }
}

// ---------------- out-proj epilogue ----------------
__global__ void outproj_epi_k(const float* __restrict__ pr, const float* __restrict__ t,
                              float* __restrict__ r, int dir) {
    int idx = blockIdx.x * blockDim.x + threadIdx.x;
    if (idx >= B_ * L_ * DM) return;
    int d = idx % DM;
    int l = (idx / DM) % L_;
    int b = idx / (DM * L_);
    int ltm = dir ? (L_ - 1 - l) : l;
    r[(size_t)(b * L_ + ltm) * (2 * DM) + dir * DM + d] = pr[idx] + t[(size_t)(b * L_ + ltm) * DM + d];
}

// ---------------- final epilogue ----------------
__global__ void final_epi_k(const float* __restrict__ pr, const float* __restrict__ x,
                            const float* __restrict__ pb, float* __restrict__ out) {
    int idx = blockIdx.x * blockDim.x + threadIdx.x;
    if (idx >= B_ * DM * L_) return;
    int l = idx % L_;
    int d = (idx / L_) % DM;
    int b = idx / (L_ * DM);
    out[idx] = x[idx] + pr[(size_t)(b * L_ + l) * DM + d] + pb[d];
}

// ---------------- launch ----------------
extern "C" void kernel_launch(void* const* d_in, const int* in_sizes, int n_in,
                              void* d_out, int out_size) {
    (void)in_sizes; (void)n_in; (void)out_size;
    const float* x      = (const float*)d_in[0];
    const float* gn_w   = (const float*)d_in[1];
    const float* gn_b   = (const float*)d_in[2];
    const float* proj_w = (const float*)d_in[3];
    const float* proj_b = (const float*)d_in[4];
    float* out = (float*)d_out;

    float *t_, *zx_, *xbc_, *dt_, *acs_, *cb_, *st_, *pv_, *y_, *r_, *pr_, *stats_;
    cudaGetSymbolAddress((void**)&t_,    g_t);
    cudaGetSymbolAddress((void**)&zx_,   g_zx);
    cudaGetSymbolAddress((void**)&xbc_,  g_xbc);
    cudaGetSymbolAddress((void**)&dt_,   g_dt);
    cudaGetSymbolAddress((void**)&acs_,  g_acs);
    cudaGetSymbolAddress((void**)&cb_,   g_cb);
    cudaGetSymbolAddress((void**)&st_,   g_st);
    cudaGetSymbolAddress((void**)&pv_,   g_pv);
    cudaGetSymbolAddress((void**)&y_,    g_y);
    cudaGetSymbolAddress((void**)&r_,    g_r);
    cudaGetSymbolAddress((void**)&pr_,   g_pr);
    cudaGetSymbolAddress((void**)&stats_,g_stats);

    gn_stats_k<<<B_, 512>>>(x, stats_);
    gn_apply_k<<<dim3(L_ / 32, DM / 32, B_), dim3(32, 8)>>>(x, gn_w, gn_b, stats_, t_);

    for (int dir = 0; dir < 2; dir++) {
        const float* in_w    = (const float*)d_in[5 + dir * 8 + 0];
        const float* conv_w  = (const float*)d_in[5 + dir * 8 + 1];
        const float* conv_b  = (const float*)d_in[5 + dir * 8 + 2];
        const float* dt_bias = (const float*)d_in[5 + dir * 8 + 3];
        const float* A_log   = (const float*)d_in[5 + dir * 8 + 4];
        const float* Dh      = (const float*)d_in[5 + dir * 8 + 5];
        const float* norm_w  = (const float*)d_in[5 + dir * 8 + 6];
        const float* out_w   = (const float*)d_in[5 + dir * 8 + 7];

        // in-projection (tf32 tensor cores)
        gemm_tf32<128,128><<<dim3((DIP + 127) / 128, (B_ * L_) / 128, 1), 256>>>(
            t_, in_w, zx_, B_ * L_, DIP, DM, DM, DM, DIP, 0, 0, 0, dir ? L_ : 0);

        conv_silu_k<<<(B_ * L_ * CD + 255) / 256, 256>>>(zx_, conv_w, conv_b, xbc_);
        dt_scan_k<<<B_ * NH * NC, CH>>>(zx_, dt_bias, A_log, dt_, acs_);

        // CB = C @ B^T per (b,c)  (tf32)
        gemm_tf32<128,64><<<dim3(CH / 64, CH / 128, B_ * NC), 256>>>(
            xbc_ + DI + DS, xbc_ + DI, cb_, CH, CH, DS, CD, CD, CH,
            (long long)CH * CD, (long long)CH * CD, (long long)CH * CH, 0);

        states_k<<<dim3(NH, NC, B_), 256>>>(xbc_, dt_, acs_, st_);
        chunkscan_k<<<(B_ * NH * HD * DS) / 256, 256>>>(st_, acs_, pv_);
        ssd_y_k<<<dim3(CH / 64, NH, B_ * NC), 256>>>(xbc_, dt_, acs_, cb_, pv_, Dh, y_);
        gate_rms_k<<<B_ * L_, 256>>>(y_, zx_, norm_w);

        // out-projection (tf32)
        gemm_tf32<128,64><<<dim3(DM / 64, (B_ * L_) / 128, 1), 256>>>(
            y_, out_w, pr_, B_ * L_, DM, DI, DI, DI, DM, 0, 0, 0, 0);
        outproj_epi_k<<<(B_ * L_ * DM + 255) / 256, 256>>>(pr_, t_, r_, dir);
    }

    // final projection (tf32)
    gemm_tf32<128,64><<<dim3(DM / 64, (B_ * L_) / 128, 1), 256>>>(
        r_, proj_w, pr_, B_ * L_, DM, 2 * DM, 2 * DM, 2 * DM, DM, 0, 0, 0, 0);
    final_epi_k<<<(B_ * DM * L_ + 255) / 256, 256>>>(pr_, x, proj_b, out);
}

// round 4
// speedup vs baseline: 1.7917x; 1.1935x over previous
#include <cuda_runtime.h>
#include <cuda_bf16.h>
#include <math.h>
#include <stdint.h>

// ---------------- problem constants ----------------
static const int B_   = 2;
static const int L_   = 2048;
static const int DM   = 256;
static const int DS   = 128;
static const int DI   = 1024;
static const int NH   = 16;
static const int HD   = 64;
static const int CD   = 1280;
static const int DIP  = 2320;
static const int CH   = 256;
static const int NC   = 8;
#define GN_EPS 1.1920928955078125e-07f
#define RMS_EPS 1e-5f

// ---------------- scratch ----------------
__device__ float g_t    [B_*L_*DM];
__device__ float g_zx   [B_*L_*DIP];
__device__ float g_xbc  [B_*L_*CD];
__device__ float g_dt   [B_*L_*NH];
__device__ float g_acs  [B_*NH*L_];
__device__ float g_cb   [B_*NC*CH*CH];
__device__ float g_st   [B_*NC*NH*HD*DS];
__device__ float g_pv   [B_*NC*NH*HD*DS];
__device__ float g_y    [B_*L_*DI];
__device__ float g_r    [B_*L_*2*DM];
__device__ float g_pr   [B_*L_*DM];
__device__ float g_stats[4];

__device__ __forceinline__ float siluf(float x) { return x / (1.f + expf(-x)); }
__device__ __forceinline__ float softplusf(float x) { return x > 20.f ? x : log1pf(expf(x)); }
__device__ __forceinline__ uint32_t f2tf32(float x) {
    uint32_t r; asm("cvt.rna.tf32.f32 %0, %1;" : "=r"(r) : "f"(x)); return r;
}
__device__ __forceinline__ float tf32v(float x) { return __uint_as_float(f2tf32(x)); }

#define MMA_TF32(acc, a, b) \
    asm volatile( \
        "mma.sync.aligned.m16n8k8.row.col.f32.tf32.tf32.f32 " \
        "{%0,%1,%2,%3},{%4,%5,%6,%7},{%8,%9},{%0,%1,%2,%3};" \
        : "+f"((acc)[0]), "+f"((acc)[1]), "+f"((acc)[2]), "+f"((acc)[3]) \
        : "r"((a)[0]), "r"((a)[1]), "r"((a)[2]), "r"((a)[3]), \
          "r"((b)[0]), "r"((b)[1]))

// ---------------- GroupNorm stats ----------------
__global__ void gn_stats_k(const float* __restrict__ x, float* __restrict__ stats) {
    int b = blockIdx.x;
    const float* xb = x + (size_t)b * DM * L_;
    double s = 0.0, ss = 0.0;
    for (int i = threadIdx.x; i < DM * L_; i += blockDim.x) {
        double v = xb[i]; s += v; ss += v * v;
    }
    __shared__ double sh[512], sh2[512];
    sh[threadIdx.x] = s; sh2[threadIdx.x] = ss;
    __syncthreads();
    for (int o = 256; o > 0; o >>= 1) {
        if ((int)threadIdx.x < o) { sh[threadIdx.x] += sh[threadIdx.x + o]; sh2[threadIdx.x] += sh2[threadIdx.x + o]; }
        __syncthreads();
    }
    if (threadIdx.x == 0) {
        double n = (double)DM * L_;
        double mu = sh[0] / n;
        double var = sh2[0] / n - mu * mu;
        stats[b * 2 + 0] = (float)mu;
        stats[b * 2 + 1] = rsqrtf((float)var + GN_EPS);
    }
}

// ---------------- GroupNorm apply + transpose ----------------
__global__ void gn_apply_k(const float* __restrict__ x, const float* __restrict__ gw,
                           const float* __restrict__ gb, const float* __restrict__ stats,
                           float* __restrict__ t) {
    int b = blockIdx.z;
    __shared__ float tile[32][33];
    int l0 = blockIdx.x * 32, d0 = blockIdx.y * 32;
    float mu = stats[b * 2], rs = stats[b * 2 + 1];
#pragma unroll
    for (int r = 0; r < 4; r++) {
        int d = d0 + threadIdx.y + r * 8;
        tile[threadIdx.y + r * 8][threadIdx.x] = x[((size_t)b * DM + d) * L_ + l0 + threadIdx.x];
    }
    __syncthreads();
    int d = d0 + threadIdx.x;
    float w = gw[d], bb = gb[d];
#pragma unroll
    for (int r = 0; r < 4; r++) {
        int l = l0 + threadIdx.y + r * 8;
        t[((size_t)b * L_ + l) * DM + d] = (tile[threadIdx.x][threadIdx.y + r * 8] - mu) * rs * w + bb;
    }
}

// ---------------- TF32 tensor-core NT GEMM ----------------
template<int BM, int BN>
__global__ void __launch_bounds__(256)
gemm_tf32(const float* __restrict__ A, const float* __restrict__ Bp,
          float* __restrict__ C, int M, int N, int K,
          int lda, int ldb, int ldc,
          long long sA, long long sB, long long sC, int revL) {
    constexpr int BK = 32;
    constexpr int T  = 256;
    constexpr int LA = BM * BK / (T * 4);
    constexpr int LB = BN * BK / (T * 4);
    constexpr int MF = BM / 32;
    constexpr int NF = BN / 32;
    __shared__ float As[BM][BK + 4];
    __shared__ float Bs[BN][BK + 4];
    int z = blockIdx.z;
    A += z * sA; Bp += z * sB; C += z * sC;
    int m0 = blockIdx.y * BM, n0 = blockIdx.x * BN;
    int tid = threadIdx.x;
    int warp = tid >> 5, lane = tid & 31;
    int wm = warp >> 2, wn = warp & 3;
    int group = lane >> 2, tig = lane & 3;
    float acc[MF][NF][4] = {};
    float4 ra[LA], rb[LB];

    auto loadA = [&](int k0) {
#pragma unroll
        for (int i = 0; i < LA; i++) {
            int e = tid + i * T;
            int mm = e / (BK / 4);
            int kc = (e % (BK / 4)) * 4;
            int gm = m0 + mm;
            float4 v = make_float4(0.f, 0.f, 0.f, 0.f);
            if (gm < M) {
                int row = gm;
                if (revL) { int bb = gm / revL; int ll = gm % revL; row = bb * revL + (revL - 1 - ll); }
                v = *reinterpret_cast<const float4*>(A + (long long)row * lda + k0 + kc);
            }
            ra[i] = v;
        }
    };
    auto loadB = [&](int k0) {
#pragma unroll
        for (int i = 0; i < LB; i++) {
            int e = tid + i * T;
            int nn = e / (BK / 4);
            int kc = (e % (BK / 4)) * 4;
            int gn = n0 + nn;
            float4 v = make_float4(0.f, 0.f, 0.f, 0.f);
            if (gn < N) v = *reinterpret_cast<const float4*>(Bp + (long long)gn * ldb + k0 + kc);
            rb[i] = v;
        }
    };
    auto storeS = [&]() {
#pragma unroll
        for (int i = 0; i < LA; i++) {
            int e = tid + i * T;
            int mm = e / (BK / 4);
            int kc = (e % (BK / 4)) * 4;
            As[mm][kc]   = tf32v(ra[i].x);
            As[mm][kc+1] = tf32v(ra[i].y);
            As[mm][kc+2] = tf32v(ra[i].z);
            As[mm][kc+3] = tf32v(ra[i].w);
        }
#pragma unroll
        for (int i = 0; i < LB; i++) {
            int e = tid + i * T;
            int nn = e / (BK / 4);
            int kc = (e % (BK / 4)) * 4;
            Bs[nn][kc]   = tf32v(rb[i].x);
            Bs[nn][kc+1] = tf32v(rb[i].y);
            Bs[nn][kc+2] = tf32v(rb[i].z);
            Bs[nn][kc+3] = tf32v(rb[i].w);
        }
    };
    auto compute = [&]() {
#pragma unroll
        for (int ks = 0; ks < BK / 8; ks++) {
            uint32_t af[MF][4], bf[NF][2];
#pragma unroll
            for (int mf = 0; mf < MF; mf++) {
                int rm = wm * (MF * 16) + mf * 16 + group;
                af[mf][0] = __float_as_uint(As[rm    ][ks * 8 + tig]);
                af[mf][1] = __float_as_uint(As[rm + 8][ks * 8 + tig]);
                af[mf][2] = __float_as_uint(As[rm    ][ks * 8 + tig + 4]);
                af[mf][3] = __float_as_uint(As[rm + 8][ks * 8 + tig + 4]);
            }
#pragma unroll
            for (int nf = 0; nf < NF; nf++) {
                int rn = wn * (NF * 8) + nf * 8 + group;
                bf[nf][0] = __float_as_uint(Bs[rn][ks * 8 + tig]);
                bf[nf][1] = __float_as_uint(Bs[rn][ks * 8 + tig + 4]);
            }
#pragma unroll
            for (int mf = 0; mf < MF; mf++)
#pragma unroll
                for (int nf = 0; nf < NF; nf++) MMA_TF32(acc[mf][nf], af[mf], bf[nf]);
        }
    };

    loadA(0); loadB(0);
    storeS();
    __syncthreads();
    for (int k0 = BK; k0 < K; k0 += BK) {
        loadA(k0); loadB(k0);
        compute();
        __syncthreads();
        storeS();
        __syncthreads();
    }
    compute();

#pragma unroll
    for (int mf = 0; mf < MF; mf++) {
#pragma unroll
        for (int nf = 0; nf < NF; nf++) {
            int gm = m0 + wm * (MF * 16) + mf * 16 + group;
            int gn = n0 + wn * (NF * 8) + nf * 8 + 2 * tig;
            if (gn < N) {
                if (gm < M)
                    *reinterpret_cast<float2*>(C + (long long)gm * ldc + gn) =
                        make_float2(acc[mf][nf][0], acc[mf][nf][1]);
                if (gm + 8 < M)
                    *reinterpret_cast<float2*>(C + (long long)(gm + 8) * ldc + gn) =
                        make_float2(acc[mf][nf][2], acc[mf][nf][3]);
            }
        }
    }
}

// ---------------- depthwise conv (k=4, causal) + SiLU ----------------
__global__ void conv_silu_k(const float* __restrict__ zx, const float* __restrict__ cw,
                            const float* __restrict__ cb, float* __restrict__ xbc) {
    int idx = blockIdx.x * blockDim.x + threadIdx.x;
    if (idx >= B_ * L_ * CD) return;
    int ch = idx % CD;
    int l  = (idx / CD) % L_;
    int b  = idx / (CD * L_);
    float acc = cb[ch];
#pragma unroll
    for (int k = 0; k < 4; k++) {
        int lp = l - 3 + k;
        if (lp >= 0) acc += cw[ch * 4 + k] * zx[(size_t)(b * L_ + lp) * DIP + DI + ch];
    }
    xbc[idx] = siluf(acc);
}

// ---------------- dt softplus + per-chunk cumsum ----------------
__global__ void dt_scan_k(const float* __restrict__ zx, const float* __restrict__ dt_bias,
                          const float* __restrict__ A_log, float* __restrict__ dt,
                          float* __restrict__ acs) {
    int bi = blockIdx.x;
    int c = bi % NC, h = (bi / NC) % NH, b = bi / (NC * NH);
    int l = threadIdx.x;
    int gl = c * CH + l;
    int row = b * L_ + gl;
    float v = zx[(size_t)row * DIP + (DIP - NH) + h] + dt_bias[h];
    float dtv = softplusf(v);
    dt[row * NH + h] = dtv;
    float a = -expf(A_log[h]) * dtv;
    __shared__ float sb[CH];
    sb[l] = a;
    __syncthreads();
    for (int off = 1; off < CH; off <<= 1) {
        float tv = (l >= off) ? sb[l - off] : 0.f;
        __syncthreads();
        sb[l] += tv;
        __syncthreads();
    }
    acs[(b * NH + h) * L_ + gl] = sb[l];
}

// ---------------- per-chunk end state via tf32 mma ----------------
// st[p,n] = sum_l (x[l,p]*w[l]) * B[l,n]; output 64x128, K=256.
__global__ void __launch_bounds__(256)
states_mma_k(const float* __restrict__ xbc, const float* __restrict__ dt,
             const float* __restrict__ acs, float* __restrict__ st) {
    int h = blockIdx.x, c = blockIdx.y, b = blockIdx.z;
    int tid = threadIdx.x;
    int warp = tid >> 5, lane = tid & 31;
    int wm = warp >> 2, wn = warp & 3;   // 2 x 4
    int group = lane >> 2, tig = lane & 3;
    __shared__ float Xs[32][72];   // [l][p]  stride%32 = 8
    __shared__ float Bs[32][136];  // [l][n]  stride%32 = 8
    __shared__ float wrow[32];
    int acsbase = (b * NH + h) * L_ + c * CH;
    float csLast = acs[acsbase + CH - 1];
    float acc[2][4][4] = {};
    for (int s0 = 0; s0 < CH; s0 += 32) {
        __syncthreads();
        if (tid < 32) {
            int row = b * L_ + c * CH + s0 + tid;
            wrow[tid] = dt[row * NH + h] * expf(csLast - acs[acsbase + s0 + tid]);
        }
        __syncthreads();
#pragma unroll
        for (int i = 0; i < 8; i++) {
            int e = tid + i * 256;
            int pp = e & 63, ss = e >> 6;
            int row = b * L_ + c * CH + s0 + ss;
            Xs[ss][pp] = tf32v(xbc[(size_t)row * CD + h * HD + pp] * wrow[ss]);
        }
#pragma unroll
        for (int i = 0; i < 16; i++) {
            int e = tid + i * 256;
            int nn = e & 127, ss = e >> 7;
            int row = b * L_ + c * CH + s0 + ss;
            Bs[ss][nn] = tf32v(xbc[(size_t)row * CD + DI + nn]);
        }
        __syncthreads();
#pragma unroll
        for (int ks = 0; ks < 4; ks++) {
            int k0 = ks * 8;
            uint32_t af[2][4], bf[4][2];
#pragma unroll
            for (int mf = 0; mf < 2; mf++) {
                int rm = wm * 32 + mf * 16 + group;
                af[mf][0] = __float_as_uint(Xs[k0 + tig    ][rm]);
                af[mf][1] = __float_as_uint(Xs[k0 + tig    ][rm + 8]);
                af[mf][2] = __float_as_uint(Xs[k0 + tig + 4][rm]);
                af[mf][3] = __float_as_uint(Xs[k0 + tig + 4][rm + 8]);
            }
#pragma unroll
            for (int nf = 0; nf < 4; nf++) {
                int rn = wn * 32 + nf * 8 + group;
                bf[nf][0] = __float_as_uint(Bs[k0 + tig    ][rn]);
                bf[nf][1] = __float_as_uint(Bs[k0 + tig + 4][rn]);
            }
#pragma unroll
            for (int mf = 0; mf < 2; mf++)
#pragma unroll
                for (int nf = 0; nf < 4; nf++) MMA_TF32(acc[mf][nf], af[mf], bf[nf]);
        }
    }
    float* base = st + (size_t)((b * NC + c) * NH + h) * HD * DS;
#pragma unroll
    for (int mf = 0; mf < 2; mf++) {
#pragma unroll
        for (int nf = 0; nf < 4; nf++) {
            int gm = wm * 32 + mf * 16 + group;
            int gn = wn * 32 + nf * 8 + 2 * tig;
            *reinterpret_cast<float2*>(base + gm * DS + gn) =
                make_float2(acc[mf][nf][0], acc[mf][nf][1]);
            *reinterpret_cast<float2*>(base + (gm + 8) * DS + gn) =
                make_float2(acc[mf][nf][2], acc[mf][nf][3]);
        }
    }
}

// ---------------- inter-chunk recurrence ----------------
__global__ void chunkscan_k(const float* __restrict__ st, const float* __restrict__ acs,
                            float* __restrict__ pv) {
    int idx = blockIdx.x * blockDim.x + threadIdx.x;
    int n = idx & (DS - 1);
    int p = (idx >> 7) & (HD - 1);
    int h = (idx >> 13) & (NH - 1);
    int b = idx >> 17;
    float S = 0.f;
    for (int c = 0; c < NC; c++) {
        size_t off = ((size_t)((b * NC + c) * NH + h) * HD + p) * DS + n;
        pv[off] = S;
        float at = acs[(b * NH + h) * L_ + c * CH + CH - 1];
        S = S * expf(at) + st[off];
    }
}

// ---------------- Y via tf32 mma: diag + off-diag accumulate, + D skip ----------------
__global__ void __launch_bounds__(256)
ssd_y_mma_k(const float* __restrict__ xbc, const float* __restrict__ dt,
            const float* __restrict__ acs, const float* __restrict__ cb,
            const float* __restrict__ pv, const float* __restrict__ Dh,
            float* __restrict__ y) {
    int lt = blockIdx.x, h = blockIdx.y, bc = blockIdx.z;
    int c = bc % NC, b = bc / NC;
    int tid = threadIdx.x;
    int warp = tid >> 5, lane = tid & 31;
    int wm = warp >> 2, wn = warp & 3;   // 2(M=32l) x 4(N=16p)
    int group = lane >> 2, tig = lane & 3;
    __shared__ float Ws[64][36];   // [l][k]  stride%32 = 4  (also used as C' in phase 2)
    __shared__ float Xs[32][72];   // [s][p]  stride%32 = 8
    __shared__ float Ps[64][36];   // [p][n]  stride%32 = 4
    __shared__ float csl[64], css[32];
    int l0 = lt * 64;
    int acsbase = (b * NH + h) * L_ + c * CH;
    if (tid < 64) csl[tid] = acs[acsbase + l0 + tid];
    const float* cbb = cb + (size_t)(b * NC + c) * CH * CH;
    float acc[2][2][4] = {};
    int nst = 2 * lt + 2;
    for (int stp = 0; stp < nst; stp++) {
        int s0 = stp * 32;
        __syncthreads();
        if (tid < 32) css[tid] = acs[acsbase + s0 + tid];
        __syncthreads();
#pragma unroll
        for (int i = 0; i < 8; i++) {
            int e = tid + i * 256;
            int j = e & 31, ii = e >> 5;
            float w = 0.f;
            if (s0 + j <= l0 + ii) w = expf(csl[ii] - css[j]) * cbb[(l0 + ii) * CH + s0 + j];
            Ws[ii][j] = tf32v(w);
        }
#pragma unroll
        for (int i = 0; i < 8; i++) {
            int e = tid + i * 256;
            int pp = e & 63, ss = e >> 6;
            int row = b * L_ + c * CH + s0 + ss;
            Xs[ss][pp] = tf32v(xbc[(size_t)row * CD + h * HD + pp] * dt[row * NH + h]);
        }
        __syncthreads();
#pragma unroll
        for (int ks = 0; ks < 4; ks++) {
            int k0 = ks * 8;
            uint32_t af[2][4], bf[2][2];
#pragma unroll
            for (int mf = 0; mf < 2; mf++) {
                int rm = wm * 32 + mf * 16 + group;
                af[mf][0] = __float_as_uint(Ws[rm    ][k0 + tig]);
                af[mf][1] = __float_as_uint(Ws[rm + 8][k0 + tig]);
                af[mf][2] = __float_as_uint(Ws[rm    ][k0 + tig + 4]);
                af[mf][3] = __float_as_uint(Ws[rm + 8][k0 + tig + 4]);
            }
#pragma unroll
            for (int nf = 0; nf < 2; nf++) {
                int rn = wn * 16 + nf * 8 + group;
                bf[nf][0] = __float_as_uint(Xs[k0 + tig    ][rn]);
                bf[nf][1] = __float_as_uint(Xs[k0 + tig + 4][rn]);
            }
#pragma unroll
            for (int mf = 0; mf < 2; mf++)
#pragma unroll
                for (int nf = 0; nf < 2; nf++) MMA_TF32(acc[mf][nf], af[mf], bf[nf]);
        }
    }
    // off-diagonal: Y[l,p] += sum_n (C[l,n]*exp(csl[l])) * pv[p,n]
    const float* pvb = pv + (size_t)((b * NC + c) * NH + h) * HD * DS;
    for (int nt = 0; nt < 4; nt++) {
        int n0 = nt * 32;
        __syncthreads();
#pragma unroll
        for (int i = 0; i < 8; i++) {
            int e = tid + i * 256;
            int j = e & 31, ii = e >> 5;
            int row = b * L_ + c * CH + l0 + ii;
            Ws[ii][j] = tf32v(xbc[(size_t)row * CD + DI + DS + n0 + j] * expf(csl[ii]));
        }
#pragma unroll
        for (int i = 0; i < 8; i++) {
            int e = tid + i * 256;
            int j = e & 31, pp = e >> 5;
            Ps[pp][j] = tf32v(pvb[pp * DS + n0 + j]);
        }
        __syncthreads();
#pragma unroll
        for (int ks = 0; ks < 4; ks++) {
            int k0 = ks * 8;
            uint32_t af[2][4], bf[2][2];
#pragma unroll
            for (int mf = 0; mf < 2; mf++) {
                int rm = wm * 32 + mf * 16 + group;
                af[mf][0] = __float_as_uint(Ws[rm    ][k0 + tig]);
                af[mf][1] = __float_as_uint(Ws[rm + 8][k0 + tig]);
                af[mf][2] = __float_as_uint(Ws[rm    ][k0 + tig + 4]);
                af[mf][3] = __float_as_uint(Ws[rm + 8][k0 + tig + 4]);
            }
#pragma unroll
            for (int nf = 0; nf < 2; nf++) {
                int rn = wn * 16 + nf * 8 + group;
                bf[nf][0] = __float_as_uint(Ps[rn][k0 + tig]);
                bf[nf][1] = __float_as_uint(Ps[rn][k0 + tig + 4]);
            }
#pragma unroll
            for (int mf = 0; mf < 2; mf++)
#pragma unroll
                for (int nf = 0; nf < 2; nf++) MMA_TF32(acc[mf][nf], af[mf], bf[nf]);
        }
    }
    float dh = Dh[h];
#pragma unroll
    for (int mf = 0; mf < 2; mf++) {
#pragma unroll
        for (int nf = 0; nf < 2; nf++) {
            int ll = l0 + wm * 32 + mf * 16 + group;
            int pp = wn * 16 + nf * 8 + 2 * tig;
#pragma unroll
            for (int rr = 0; rr < 2; rr++) {
                int row = b * L_ + c * CH + ll + rr * 8;
                float2 xr = *reinterpret_cast<const float2*>(
                    xbc + (size_t)row * CD + h * HD + pp);
                *reinterpret_cast<float2*>(y + (size_t)row * DI + h * HD + pp) =
                    make_float2(acc[mf][nf][rr * 2 + 0] + xr.x * dh,
                                acc[mf][nf][rr * 2 + 1] + xr.y * dh);
            }
        }
    }
}

// ---------------- gating + RMSNorm ----------------
__global__ void gate_rms_k(float* __restrict__ y, const float* __restrict__ zx,
                           const float* __restrict__ nw) {
    int row = blockIdx.x;
    int tid = threadIdx.x;
    float v[4];
    float ss = 0.f;
#pragma unroll
    for (int i = 0; i < 4; i++) {
        int d = i * 256 + tid;
        float z = zx[(size_t)row * DIP + d];
        float yy = y[(size_t)row * DI + d] * siluf(z);
        v[i] = yy;
        ss += yy * yy;
    }
    __shared__ float sh[256];
    sh[tid] = ss;
    __syncthreads();
    for (int o = 128; o > 0; o >>= 1) {
        if (tid < o) sh[tid] += sh[tid + o];
        __syncthreads();
    }
    float scale = rsqrtf(sh[0] / DI + RMS_EPS);
#pragma unroll
    for (int i = 0; i < 4; i++) {
        int d = i * 256 + tid;
        y[(size_t)row * DI + d] = v[i] * scale * nw[d];
    }
}

// ---------------- out-proj epilogue ----------------
__global__ void outproj_epi_k(const float* __restrict__ pr, const float* __restrict__ t,
                              float* __restrict__ r, int dir) {
    int idx = blockIdx.x * blockDim.x + threadIdx.x;
    if (idx >= B_ * L_ * DM) return;
    int d = idx % DM;
    int l = (idx / DM) % L_;
    int b = idx / (DM * L_);
    int ltm = dir ? (L_ - 1 - l) : l;
    r[(size_t)(b * L_ + ltm) * (2 * DM) + dir * DM + d] = pr[idx] + t[(size_t)(b * L_ + ltm) * DM + d];
}

// ---------------- final epilogue ----------------
__global__ void final_epi_k(const float* __restrict__ pr, const float* __restrict__ x,
                            const float* __restrict__ pb, float* __restrict__ out) {
    int idx = blockIdx.x * blockDim.x + threadIdx.x;
    if (idx >= B_ * DM * L_) return;
    int l = idx % L_;
    int d = (idx / L_) % DM;
    int b = idx / (L_ * DM);
    out[idx] = x[idx] + pr[(size_t)(b * L_ + l) * DM + d] + pb[d];
}

// ---------------- launch ----------------
extern "C" void kernel_launch(void* const* d_in, const int* in_sizes, int n_in,
                              void* d_out, int out_size) {
    (void)in_sizes; (void)n_in; (void)out_size;
    const float* x      = (const float*)d_in[0];
    const float* gn_w   = (const float*)d_in[1];
    const float* gn_b   = (const float*)d_in[2];
    const float* proj_w = (const float*)d_in[3];
    const float* proj_b = (const float*)d_in[4];
    float* out = (float*)d_out;

    float *t_, *zx_, *xbc_, *dt_, *acs_, *cb_, *st_, *pv_, *y_, *r_, *pr_, *stats_;
    cudaGetSymbolAddress((void**)&t_,    g_t);
    cudaGetSymbolAddress((void**)&zx_,   g_zx);
    cudaGetSymbolAddress((void**)&xbc_,  g_xbc);
    cudaGetSymbolAddress((void**)&dt_,   g_dt);
    cudaGetSymbolAddress((void**)&acs_,  g_acs);
    cudaGetSymbolAddress((void**)&cb_,   g_cb);
    cudaGetSymbolAddress((void**)&st_,   g_st);
    cudaGetSymbolAddress((void**)&pv_,   g_pv);
    cudaGetSymbolAddress((void**)&y_,    g_y);
    cudaGetSymbolAddress((void**)&r_,    g_r);
    cudaGetSymbolAddress((void**)&pr_,   g_pr);
    cudaGetSymbolAddress((void**)&stats_,g_stats);

    gn_stats_k<<<B_, 512>>>(x, stats_);
    gn_apply_k<<<dim3(L_ / 32, DM / 32, B_), dim3(32, 8)>>>(x, gn_w, gn_b, stats_, t_);

    for (int dir = 0; dir < 2; dir++) {
        const float* in_w    = (const float*)d_in[5 + dir * 8 + 0];
        const float* conv_w  = (const float*)d_in[5 + dir * 8 + 1];
        const float* conv_b  = (const float*)d_in[5 + dir * 8 + 2];
        const float* dt_bias = (const float*)d_in[5 + dir * 8 + 3];
        const float* A_log   = (const float*)d_in[5 + dir * 8 + 4];
        const float* Dh      = (const float*)d_in[5 + dir * 8 + 5];
        const float* norm_w  = (const float*)d_in[5 + dir * 8 + 6];
        const float* out_w   = (const float*)d_in[5 + dir * 8 + 7];

        gemm_tf32<128,128><<<dim3((DIP + 127) / 128, (B_ * L_) / 128, 1), 256>>>(
            t_, in_w, zx_, B_ * L_, DIP, DM, DM, DM, DIP, 0, 0, 0, dir ? L_ : 0);

        conv_silu_k<<<(B_ * L_ * CD + 255) / 256, 256>>>(zx_, conv_w, conv_b, xbc_);
        dt_scan_k<<<B_ * NH * NC, CH>>>(zx_, dt_bias, A_log, dt_, acs_);

        gemm_tf32<128,64><<<dim3(CH / 64, CH / 128, B_ * NC), 256>>>(
            xbc_ + DI + DS, xbc_ + DI, cb_, CH, CH, DS, CD, CD, CH,
            (long long)CH * CD, (long long)CH * CD, (long long)CH * CH, 0);

        states_mma_k<<<dim3(NH, NC, B_), 256>>>(xbc_, dt_, acs_, st_);
        chunkscan_k<<<(B_ * NH * HD * DS) / 256, 256>>>(st_, acs_, pv_);
        ssd_y_mma_k<<<dim3(CH / 64, NH, B_ * NC), 256>>>(xbc_, dt_, acs_, cb_, pv_, Dh, y_);
        gate_rms_k<<<B_ * L_, 256>>>(y_, zx_, norm_w);

        gemm_tf32<128,64><<<dim3(DM / 64, (B_ * L_) / 128, 1), 256>>>(
            y_, out_w, pr_, B_ * L_, DM, DI, DI, DI, DM, 0, 0, 0, 0);
        outproj_epi_k<<<(B_ * L_ * DM + 255) / 256, 256>>>(pr_, t_, r_, dir);
    }

    gemm_tf32<128,64><<<dim3(DM / 64, (B_ * L_) / 128, 1), 256>>>(
        r_, proj_w, pr_, B_ * L_, DM, 2 * DM, 2 * DM, 2 * DM, DM, 0, 0, 0, 0);
    final_epi_k<<<(B_ * DM * L_ + 255) / 256, 256>>>(pr_, x, proj_b, out);
}

// round 5
// speedup vs baseline: 1.8062x; 1.0081x over previous
#include <cuda_runtime.h>
#include <cuda_bf16.h>
#include <math.h>
#include <stdint.h>

// ---------------- problem constants ----------------
static const int B_   = 2;
static const int L_   = 2048;
static const int DM   = 256;
static const int DS   = 128;
static const int DI   = 1024;
static const int NH   = 16;
static const int HD   = 64;
static const int CD   = 1280;
static const int DIP  = 2320;
static const int CH   = 256;
static const int NC   = 8;
#define GN_EPS 1.1920928955078125e-07f
#define RMS_EPS 1e-5f

// per-direction strides
#define SZ_ZX   ((long long)B_*L_*DIP)
#define SZ_XBC  ((long long)B_*L_*CD)
#define SZ_DT   ((long long)B_*L_*NH)
#define SZ_ACS  ((long long)B_*NH*L_)
#define SZ_CB   ((long long)B_*NC*CH*CH)
#define SZ_ST   ((long long)B_*NC*NH*HD*DS)
#define SZ_Y    ((long long)B_*L_*DI)

// ---------------- scratch (doubled for 2 directions) ----------------
__device__ float g_t    [B_*L_*DM];
__device__ float g_zx   [2*B_*L_*DIP];
__device__ float g_xbc  [2*B_*L_*CD];
__device__ float g_dt   [2*B_*L_*NH];
__device__ float g_acs  [2*B_*NH*L_];
__device__ float g_cb   [2*B_*NC*CH*CH];
__device__ float g_st   [2*B_*NC*NH*HD*DS];
__device__ float g_pv   [2*B_*NC*NH*HD*DS];
__device__ float g_y    [2*B_*L_*DI];
__device__ float g_r    [B_*L_*2*DM];
__device__ float g_stats[4];

__device__ __forceinline__ float siluf(float x) { return x / (1.f + expf(-x)); }
__device__ __forceinline__ float softplusf(float x) { return x > 20.f ? x : log1pf(expf(x)); }
__device__ __forceinline__ uint32_t f2tf32(float x) {
    uint32_t r; asm("cvt.rna.tf32.f32 %0, %1;" : "=r"(r) : "f"(x)); return r;
}
__device__ __forceinline__ float tf32v(float x) { return __uint_as_float(f2tf32(x)); }

#define MMA_TF32(acc, a, b) \
    asm volatile( \
        "mma.sync.aligned.m16n8k8.row.col.f32.tf32.tf32.f32 " \
        "{%0,%1,%2,%3},{%4,%5,%6,%7},{%8,%9},{%0,%1,%2,%3};" \
        : "+f"((acc)[0]), "+f"((acc)[1]), "+f"((acc)[2]), "+f"((acc)[3]) \
        : "r"((a)[0]), "r"((a)[1]), "r"((a)[2]), "r"((a)[3]), \
          "r"((b)[0]), "r"((b)[1]))

// ---------------- GroupNorm stats ----------------
__global__ void gn_stats_k(const float* __restrict__ x, float* __restrict__ stats) {
    int b = blockIdx.x;
    const float* xb = x + (size_t)b * DM * L_;
    double s = 0.0, ss = 0.0;
    for (int i = threadIdx.x; i < DM * L_; i += blockDim.x) {
        double v = xb[i]; s += v; ss += v * v;
    }
    __shared__ double sh[512], sh2[512];
    sh[threadIdx.x] = s; sh2[threadIdx.x] = ss;
    __syncthreads();
    for (int o = 256; o > 0; o >>= 1) {
        if ((int)threadIdx.x < o) { sh[threadIdx.x] += sh[threadIdx.x + o]; sh2[threadIdx.x] += sh2[threadIdx.x + o]; }
        __syncthreads();
    }
    if (threadIdx.x == 0) {
        double n = (double)DM * L_;
        double mu = sh[0] / n;
        double var = sh2[0] / n - mu * mu;
        stats[b * 2 + 0] = (float)mu;
        stats[b * 2 + 1] = rsqrtf((float)var + GN_EPS);
    }
}

// ---------------- GroupNorm apply + transpose ----------------
__global__ void gn_apply_k(const float* __restrict__ x, const float* __restrict__ gw,
                           const float* __restrict__ gb, const float* __restrict__ stats,
                           float* __restrict__ t) {
    int b = blockIdx.z;
    __shared__ float tile[32][33];
    int l0 = blockIdx.x * 32, d0 = blockIdx.y * 32;
    float mu = stats[b * 2], rs = stats[b * 2 + 1];
#pragma unroll
    for (int r = 0; r < 4; r++) {
        int d = d0 + threadIdx.y + r * 8;
        tile[threadIdx.y + r * 8][threadIdx.x] = x[((size_t)b * DM + d) * L_ + l0 + threadIdx.x];
    }
    __syncthreads();
    int d = d0 + threadIdx.x;
    float w = gw[d], bb = gb[d];
#pragma unroll
    for (int r = 0; r < 4; r++) {
        int l = l0 + threadIdx.y + r * 8;
        t[((size_t)b * L_ + l) * DM + d] = (tile[threadIdx.x][threadIdx.y + r * 8] - mu) * rs * w + bb;
    }
}

// ---------------- TF32 tensor-core NT GEMM, dir-batched, fused epilogues ----
// MODE 0: plain store. MODE 1: out-proj epilogue (scatter into r + residual t).
// MODE 2: final epilogue (transposed store + x + bias).
template<int BM, int BN, int MODE>
__global__ void __launch_bounds__(256)
gemm_tf32(const float* __restrict__ A, const float* __restrict__ B0,
          const float* __restrict__ B1, float* __restrict__ C,
          int M, int N, int K, int lda, int ldb, int ldc,
          long long sA, long long sB, long long sC,
          int zPerDir, long long dA, long long dC, int revL,
          const float* __restrict__ extra, const float* __restrict__ bias) {
    constexpr int BK = 32;
    constexpr int T  = 256;
    constexpr int LA = BM * BK / (T * 4);
    constexpr int LB = BN * BK / (T * 4);
    constexpr int MF = BM / 32;
    constexpr int NF = BN / 32;
    __shared__ float As[BM][BK + 4];
    __shared__ float Bs[BN][BK + 4];
    int z = blockIdx.z;
    int dir = z / zPerDir, zz = z % zPerDir;
    const float* Ap = A + dir * dA + zz * sA;
    const float* Bp = (dir ? B1 : B0) + zz * sB;
    float* Cp = C + dir * dC + zz * sC;
    int rev = dir ? revL : 0;
    int m0 = blockIdx.y * BM, n0 = blockIdx.x * BN;
    int tid = threadIdx.x;
    int warp = tid >> 5, lane = tid & 31;
    int wm = warp >> 2, wn = warp & 3;
    int group = lane >> 2, tig = lane & 3;
    float acc[MF][NF][4] = {};
    float4 ra[LA], rb[LB];

    auto loadA = [&](int k0) {
#pragma unroll
        for (int i = 0; i < LA; i++) {
            int e = tid + i * T;
            int mm = e / (BK / 4);
            int kc = (e % (BK / 4)) * 4;
            int gm = m0 + mm;
            float4 v = make_float4(0.f, 0.f, 0.f, 0.f);
            if (gm < M) {
                int row = gm;
                if (rev) { int bb = gm / rev; int ll = gm % rev; row = bb * rev + (rev - 1 - ll); }
                v = *reinterpret_cast<const float4*>(Ap + (long long)row * lda + k0 + kc);
            }
            ra[i] = v;
        }
    };
    auto loadB = [&](int k0) {
#pragma unroll
        for (int i = 0; i < LB; i++) {
            int e = tid + i * T;
            int nn = e / (BK / 4);
            int kc = (e % (BK / 4)) * 4;
            int gn = n0 + nn;
            float4 v = make_float4(0.f, 0.f, 0.f, 0.f);
            if (gn < N) v = *reinterpret_cast<const float4*>(Bp + (long long)gn * ldb + k0 + kc);
            rb[i] = v;
        }
    };
    auto storeS = [&]() {
#pragma unroll
        for (int i = 0; i < LA; i++) {
            int e = tid + i * T;
            int mm = e / (BK / 4);
            int kc = (e % (BK / 4)) * 4;
            As[mm][kc]   = tf32v(ra[i].x);
            As[mm][kc+1] = tf32v(ra[i].y);
            As[mm][kc+2] = tf32v(ra[i].z);
            As[mm][kc+3] = tf32v(ra[i].w);
        }
#pragma unroll
        for (int i = 0; i < LB; i++) {
            int e = tid + i * T;
            int nn = e / (BK / 4);
            int kc = (e % (BK / 4)) * 4;
            Bs[nn][kc]   = tf32v(rb[i].x);
            Bs[nn][kc+1] = tf32v(rb[i].y);
            Bs[nn][kc+2] = tf32v(rb[i].z);
            Bs[nn][kc+3] = tf32v(rb[i].w);
        }
    };
    auto compute = [&]() {
#pragma unroll
        for (int ks = 0; ks < BK / 8; ks++) {
            uint32_t af[MF][4], bf[NF][2];
#pragma unroll
            for (int mf = 0; mf < MF; mf++) {
                int rm = wm * (MF * 16) + mf * 16 + group;
                af[mf][0] = __float_as_uint(As[rm    ][ks * 8 + tig]);
                af[mf][1] = __float_as_uint(As[rm + 8][ks * 8 + tig]);
                af[mf][2] = __float_as_uint(As[rm    ][ks * 8 + tig + 4]);
                af[mf][3] = __float_as_uint(As[rm + 8][ks * 8 + tig + 4]);
            }
#pragma unroll
            for (int nf = 0; nf < NF; nf++) {
                int rn = wn * (NF * 8) + nf * 8 + group;
                bf[nf][0] = __float_as_uint(Bs[rn][ks * 8 + tig]);
                bf[nf][1] = __float_as_uint(Bs[rn][ks * 8 + tig + 4]);
            }
#pragma unroll
            for (int mf = 0; mf < MF; mf++)
#pragma unroll
                for (int nf = 0; nf < NF; nf++) MMA_TF32(acc[mf][nf], af[mf], bf[nf]);
        }
    };

    loadA(0); loadB(0);
    storeS();
    __syncthreads();
    for (int k0 = BK; k0 < K; k0 += BK) {
        loadA(k0); loadB(k0);
        compute();
        __syncthreads();
        storeS();
        __syncthreads();
    }
    compute();

#pragma unroll
    for (int mf = 0; mf < MF; mf++) {
#pragma unroll
        for (int nf = 0; nf < NF; nf++) {
            int gn = n0 + wn * (NF * 8) + nf * 8 + 2 * tig;
#pragma unroll
            for (int rr = 0; rr < 2; rr++) {
                int gm = m0 + wm * (MF * 16) + mf * 16 + group + rr * 8;
                float a0 = acc[mf][nf][rr * 2 + 0], a1 = acc[mf][nf][rr * 2 + 1];
                if (MODE == 0) {
                    if (gm < M && gn < N)
                        *reinterpret_cast<float2*>(Cp + (long long)gm * ldc + gn) =
                            make_float2(a0, a1);
                } else if (MODE == 1) {
                    int b = gm / L_, l = gm % L_;
                    int ltm = dir ? (L_ - 1 - l) : l;
                    long long base = (long long)(b * L_ + ltm);
                    float2 tv = *reinterpret_cast<const float2*>(extra + base * DM + gn);
                    *reinterpret_cast<float2*>(C + base * (2 * DM) + dir * DM + gn) =
                        make_float2(a0 + tv.x, a1 + tv.y);
                } else {
                    int b = gm / L_, l = gm % L_;
                    long long i0 = ((long long)(b * DM + gn)) * L_ + l;
                    long long i1 = ((long long)(b * DM + gn + 1)) * L_ + l;
                    C[i0] = extra[i0] + bias[gn] + a0;
                    C[i1] = extra[i1] + bias[gn + 1] + a1;
                }
            }
        }
    }
}

// ---------------- depthwise conv + SiLU (dir-batched) ----------------
__global__ void conv_silu_k(const float* __restrict__ zx,
                            const float* __restrict__ cw0, const float* __restrict__ cb0,
                            const float* __restrict__ cw1, const float* __restrict__ cb1,
                            float* __restrict__ xbc) {
    long long idx = (long long)blockIdx.x * blockDim.x + threadIdx.x;
    if (idx >= 2LL * B_ * L_ * CD) return;
    int ch = idx % CD;
    int l  = (idx / CD) % L_;
    long long rest = idx / ((long long)CD * L_);
    int b = rest % B_;
    int dir = rest / B_;
    const float* cw = dir ? cw1 : cw0;
    const float* cb = dir ? cb1 : cb0;
    const float* zxd = zx + dir * SZ_ZX;
    float acc = cb[ch];
#pragma unroll
    for (int k = 0; k < 4; k++) {
        int lp = l - 3 + k;
        if (lp >= 0) acc += cw[ch * 4 + k] * zxd[(size_t)(b * L_ + lp) * DIP + DI + ch];
    }
    xbc[dir * SZ_XBC + ((size_t)(b * L_ + l)) * CD + ch] = siluf(acc);
}

// ---------------- dt softplus + per-chunk cumsum (dir-batched) ----------------
__global__ void dt_scan_k(const float* __restrict__ zx,
                          const float* __restrict__ db0, const float* __restrict__ al0,
                          const float* __restrict__ db1, const float* __restrict__ al1,
                          float* __restrict__ dt, float* __restrict__ acs) {
    int bi = blockIdx.x;
    int dir = bi / (B_ * NH * NC);
    bi %= B_ * NH * NC;
    int c = bi % NC, h = (bi / NC) % NH, b = bi / (NC * NH);
    const float* dt_bias = dir ? db1 : db0;
    const float* A_log   = dir ? al1 : al0;
    int l = threadIdx.x;
    int gl = c * CH + l;
    int row = b * L_ + gl;
    float v = zx[dir * SZ_ZX + (size_t)row * DIP + (DIP - NH) + h] + dt_bias[h];
    float dtv = softplusf(v);
    dt[dir * SZ_DT + (size_t)row * NH + h] = dtv;
    float a = -expf(A_log[h]) * dtv;
    __shared__ float sb[CH];
    sb[l] = a;
    __syncthreads();
    for (int off = 1; off < CH; off <<= 1) {
        float tv = (l >= off) ? sb[l - off] : 0.f;
        __syncthreads();
        sb[l] += tv;
        __syncthreads();
    }
    acs[dir * SZ_ACS + (size_t)(b * NH + h) * L_ + gl] = sb[l];
}

// ---------------- per-chunk end state via tf32 mma (dir-batched) ----------------
__global__ void __launch_bounds__(256)
states_mma_k(const float* __restrict__ xbc, const float* __restrict__ dt,
             const float* __restrict__ acs, float* __restrict__ st) {
    int h = blockIdx.x, c = blockIdx.y;
    int dir = blockIdx.z / B_, b = blockIdx.z % B_;
    const float* xbcd = xbc + dir * SZ_XBC;
    const float* dtd  = dt  + dir * SZ_DT;
    const float* acsd = acs + dir * SZ_ACS;
    int tid = threadIdx.x;
    int warp = tid >> 5, lane = tid & 31;
    int wm = warp >> 2, wn = warp & 3;
    int group = lane >> 2, tig = lane & 3;
    __shared__ float Xs[32][72];
    __shared__ float Bs[32][136];
    __shared__ float wrow[32];
    int acsbase = (b * NH + h) * L_ + c * CH;
    float csLast = acsd[acsbase + CH - 1];
    float acc[2][4][4] = {};
    for (int s0 = 0; s0 < CH; s0 += 32) {
        __syncthreads();
        if (tid < 32) {
            int row = b * L_ + c * CH + s0 + tid;
            wrow[tid] = dtd[(size_t)row * NH + h] * expf(csLast - acsd[acsbase + s0 + tid]);
        }
        __syncthreads();
#pragma unroll
        for (int i = 0; i < 8; i++) {
            int e = tid + i * 256;
            int pp = e & 63, ss = e >> 6;
            int row = b * L_ + c * CH + s0 + ss;
            Xs[ss][pp] = tf32v(xbcd[(size_t)row * CD + h * HD + pp] * wrow[ss]);
        }
#pragma unroll
        for (int i = 0; i < 16; i++) {
            int e = tid + i * 256;
            int nn = e & 127, ss = e >> 7;
            int row = b * L_ + c * CH + s0 + ss;
            Bs[ss][nn] = tf32v(xbcd[(size_t)row * CD + DI + nn]);
        }
        __syncthreads();
#pragma unroll
        for (int ks = 0; ks < 4; ks++) {
            int k0 = ks * 8;
            uint32_t af[2][4], bf[4][2];
#pragma unroll
            for (int mf = 0; mf < 2; mf++) {
                int rm = wm * 32 + mf * 16 + group;
                af[mf][0] = __float_as_uint(Xs[k0 + tig    ][rm]);
                af[mf][1] = __float_as_uint(Xs[k0 + tig    ][rm + 8]);
                af[mf][2] = __float_as_uint(Xs[k0 + tig + 4][rm]);
                af[mf][3] = __float_as_uint(Xs[k0 + tig + 4][rm + 8]);
            }
#pragma unroll
            for (int nf = 0; nf < 4; nf++) {
                int rn = wn * 32 + nf * 8 + group;
                bf[nf][0] = __float_as_uint(Bs[k0 + tig    ][rn]);
                bf[nf][1] = __float_as_uint(Bs[k0 + tig + 4][rn]);
            }
#pragma unroll
            for (int mf = 0; mf < 2; mf++)
#pragma unroll
                for (int nf = 0; nf < 4; nf++) MMA_TF32(acc[mf][nf], af[mf], bf[nf]);
        }
    }
    float* base = st + dir * SZ_ST + (size_t)((b * NC + c) * NH + h) * HD * DS;
#pragma unroll
    for (int mf = 0; mf < 2; mf++) {
#pragma unroll
        for (int nf = 0; nf < 4; nf++) {
            int gm = wm * 32 + mf * 16 + group;
            int gn = wn * 32 + nf * 8 + 2 * tig;
            *reinterpret_cast<float2*>(base + gm * DS + gn) =
                make_float2(acc[mf][nf][0], acc[mf][nf][1]);
            *reinterpret_cast<float2*>(base + (gm + 8) * DS + gn) =
                make_float2(acc[mf][nf][2], acc[mf][nf][3]);
        }
    }
}

// ---------------- inter-chunk recurrence (dir-batched) ----------------
__global__ void chunkscan_k(const float* __restrict__ st, const float* __restrict__ acs,
                            float* __restrict__ pv) {
    int idx = blockIdx.x * blockDim.x + threadIdx.x;
    int n = idx & (DS - 1);
    int p = (idx >> 7) & (HD - 1);
    int h = (idx >> 13) & (NH - 1);
    int b = (idx >> 17) & (B_ - 1);
    int dir = idx >> 18;
    const float* std_ = st + dir * SZ_ST;
    const float* acsd = acs + dir * SZ_ACS;
    float* pvd = pv + dir * SZ_ST;
    float S = 0.f;
    for (int c = 0; c < NC; c++) {
        size_t off = ((size_t)((b * NC + c) * NH + h) * HD + p) * DS + n;
        pvd[off] = S;
        float at = acsd[(b * NH + h) * L_ + c * CH + CH - 1];
        S = S * expf(at) + std_[off];
    }
}

// ---------------- Y via tf32 mma (dir-batched) ----------------
__global__ void __launch_bounds__(256)
ssd_y_mma_k(const float* __restrict__ xbc, const float* __restrict__ dt,
            const float* __restrict__ acs, const float* __restrict__ cb,
            const float* __restrict__ pv,
            const float* __restrict__ Dh0, const float* __restrict__ Dh1,
            float* __restrict__ y) {
    int lt = blockIdx.x, h = blockIdx.y;
    int dir = blockIdx.z / (B_ * NC);
    int bc = blockIdx.z % (B_ * NC);
    int c = bc % NC, b = bc / NC;
    const float* xbcd = xbc + dir * SZ_XBC;
    const float* dtd  = dt  + dir * SZ_DT;
    const float* acsd = acs + dir * SZ_ACS;
    const float* Dh   = dir ? Dh1 : Dh0;
    int tid = threadIdx.x;
    int warp = tid >> 5, lane = tid & 31;
    int wm = warp >> 2, wn = warp & 3;
    int group = lane >> 2, tig = lane & 3;
    __shared__ float Ws[64][36];
    __shared__ float Xs[32][72];
    __shared__ float Ps[64][36];
    __shared__ float csl[64], css[32];
    int l0 = lt * 64;
    int acsbase = (b * NH + h) * L_ + c * CH;
    if (tid < 64) csl[tid] = acsd[acsbase + l0 + tid];
    const float* cbb = cb + dir * SZ_CB + (size_t)(b * NC + c) * CH * CH;
    float acc[2][2][4] = {};
    int nst = 2 * lt + 2;
    for (int stp = 0; stp < nst; stp++) {
        int s0 = stp * 32;
        __syncthreads();
        if (tid < 32) css[tid] = acsd[acsbase + s0 + tid];
        __syncthreads();
#pragma unroll
        for (int i = 0; i < 8; i++) {
            int e = tid + i * 256;
            int j = e & 31, ii = e >> 5;
            float w = 0.f;
            if (s0 + j <= l0 + ii) w = expf(csl[ii] - css[j]) * cbb[(l0 + ii) * CH + s0 + j];
            Ws[ii][j] = tf32v(w);
        }
#pragma unroll
        for (int i = 0; i < 8; i++) {
            int e = tid + i * 256;
            int pp = e & 63, ss = e >> 6;
            int row = b * L_ + c * CH + s0 + ss;
            Xs[ss][pp] = tf32v(xbcd[(size_t)row * CD + h * HD + pp] * dtd[(size_t)row * NH + h]);
        }
        __syncthreads();
#pragma unroll
        for (int ks = 0; ks < 4; ks++) {
            int k0 = ks * 8;
            uint32_t af[2][4], bf[2][2];
#pragma unroll
            for (int mf = 0; mf < 2; mf++) {
                int rm = wm * 32 + mf * 16 + group;
                af[mf][0] = __float_as_uint(Ws[rm    ][k0 + tig]);
                af[mf][1] = __float_as_uint(Ws[rm + 8][k0 + tig]);
                af[mf][2] = __float_as_uint(Ws[rm    ][k0 + tig + 4]);
                af[mf][3] = __float_as_uint(Ws[rm + 8][k0 + tig + 4]);
            }
#pragma unroll
            for (int nf = 0; nf < 2; nf++) {
                int rn = wn * 16 + nf * 8 + group;
                bf[nf][0] = __float_as_uint(Xs[k0 + tig    ][rn]);
                bf[nf][1] = __float_as_uint(Xs[k0 + tig + 4][rn]);
            }
#pragma unroll
            for (int mf = 0; mf < 2; mf++)
#pragma unroll
                for (int nf = 0; nf < 2; nf++) MMA_TF32(acc[mf][nf], af[mf], bf[nf]);
        }
    }
    const float* pvb = pv + dir * SZ_ST + (size_t)((b * NC + c) * NH + h) * HD * DS;
    for (int nt = 0; nt < 4; nt++) {
        int n0 = nt * 32;
        __syncthreads();
#pragma unroll
        for (int i = 0; i < 8; i++) {
            int e = tid + i * 256;
            int j = e & 31, ii = e >> 5;
            int row = b * L_ + c * CH + l0 + ii;
            Ws[ii][j] = tf32v(xbcd[(size_t)row * CD + DI + DS + n0 + j] * expf(csl[ii]));
        }
#pragma unroll
        for (int i = 0; i < 8; i++) {
            int e = tid + i * 256;
            int j = e & 31, pp = e >> 5;
            Ps[pp][j] = tf32v(pvb[pp * DS + n0 + j]);
        }
        __syncthreads();
#pragma unroll
        for (int ks = 0; ks < 4; ks++) {
            int k0 = ks * 8;
            uint32_t af[2][4], bf[2][2];
#pragma unroll
            for (int mf = 0; mf < 2; mf++) {
                int rm = wm * 32 + mf * 16 + group;
                af[mf][0] = __float_as_uint(Ws[rm    ][k0 + tig]);
                af[mf][1] = __float_as_uint(Ws[rm + 8][k0 + tig]);
                af[mf][2] = __float_as_uint(Ws[rm    ][k0 + tig + 4]);
                af[mf][3] = __float_as_uint(Ws[rm + 8][k0 + tig + 4]);
            }
#pragma unroll
            for (int nf = 0; nf < 2; nf++) {
                int rn = wn * 16 + nf * 8 + group;
                bf[nf][0] = __float_as_uint(Ps[rn][k0 + tig]);
                bf[nf][1] = __float_as_uint(Ps[rn][k0 + tig + 4]);
            }
#pragma unroll
            for (int mf = 0; mf < 2; mf++)
#pragma unroll
                for (int nf = 0; nf < 2; nf++) MMA_TF32(acc[mf][nf], af[mf], bf[nf]);
        }
    }
    float dh = Dh[h];
    float* yd = y + dir * SZ_Y;
#pragma unroll
    for (int mf = 0; mf < 2; mf++) {
#pragma unroll
        for (int nf = 0; nf < 2; nf++) {
            int ll = l0 + wm * 32 + mf * 16 + group;
            int pp = wn * 16 + nf * 8 + 2 * tig;
#pragma unroll
            for (int rr = 0; rr < 2; rr++) {
                int row = b * L_ + c * CH + ll + rr * 8;
                float2 xr = *reinterpret_cast<const float2*>(
                    xbcd + (size_t)row * CD + h * HD + pp);
                *reinterpret_cast<float2*>(yd + (size_t)row * DI + h * HD + pp) =
                    make_float2(acc[mf][nf][rr * 2 + 0] + xr.x * dh,
                                acc[mf][nf][rr * 2 + 1] + xr.y * dh);
            }
        }
    }
}

// ---------------- gating + RMSNorm (dir-batched) ----------------
__global__ void gate_rms_k(float* __restrict__ y, const float* __restrict__ zx,
                           const float* __restrict__ nw0, const float* __restrict__ nw1) {
    int row = blockIdx.x;
    int dir = row / (B_ * L_);
    row %= B_ * L_;
    const float* nw = dir ? nw1 : nw0;
    float* yd = y + dir * SZ_Y;
    const float* zxd = zx + dir * SZ_ZX;
    int tid = threadIdx.x;
    float v[4];
    float ss = 0.f;
#pragma unroll
    for (int i = 0; i < 4; i++) {
        int d = i * 256 + tid;
        float z = zxd[(size_t)row * DIP + d];
        float yy = yd[(size_t)row * DI + d] * siluf(z);
        v[i] = yy;
        ss += yy * yy;
    }
    __shared__ float sh[256];
    sh[tid] = ss;
    __syncthreads();
    for (int o = 128; o > 0; o >>= 1) {
        if (tid < o) sh[tid] += sh[tid + o];
        __syncthreads();
    }
    float scale = rsqrtf(sh[0] / DI + RMS_EPS);
#pragma unroll
    for (int i = 0; i < 4; i++) {
        int d = i * 256 + tid;
        yd[(size_t)row * DI + d] = v[i] * scale * nw[d];
    }
}

// ---------------- launch ----------------
extern "C" void kernel_launch(void* const* d_in, const int* in_sizes, int n_in,
                              void* d_out, int out_size) {
    (void)in_sizes; (void)n_in; (void)out_size;
    const float* x      = (const float*)d_in[0];
    const float* gn_w   = (const float*)d_in[1];
    const float* gn_b   = (const float*)d_in[2];
    const float* proj_w = (const float*)d_in[3];
    const float* proj_b = (const float*)d_in[4];
    const float* fw[8], *bw[8];
    for (int i = 0; i < 8; i++) { fw[i] = (const float*)d_in[5 + i]; bw[i] = (const float*)d_in[13 + i]; }
    float* out = (float*)d_out;

    float *t_, *zx_, *xbc_, *dt_, *acs_, *cb_, *st_, *pv_, *y_, *r_, *stats_;
    cudaGetSymbolAddress((void**)&t_,    g_t);
    cudaGetSymbolAddress((void**)&zx_,   g_zx);
    cudaGetSymbolAddress((void**)&xbc_,  g_xbc);
    cudaGetSymbolAddress((void**)&dt_,   g_dt);
    cudaGetSymbolAddress((void**)&acs_,  g_acs);
    cudaGetSymbolAddress((void**)&cb_,   g_cb);
    cudaGetSymbolAddress((void**)&st_,   g_st);
    cudaGetSymbolAddress((void**)&pv_,   g_pv);
    cudaGetSymbolAddress((void**)&y_,    g_y);
    cudaGetSymbolAddress((void**)&r_,    g_r);
    cudaGetSymbolAddress((void**)&stats_,g_stats);

    gn_stats_k<<<B_, 512>>>(x, stats_);
    gn_apply_k<<<dim3(L_ / 32, DM / 32, B_), dim3(32, 8)>>>(x, gn_w, gn_b, stats_, t_);

    // in-projection, both dirs (dir1 rows time-reversed)
    gemm_tf32<128,128,0><<<dim3((DIP + 127) / 128, (B_ * L_) / 128, 2), 256>>>(
        t_, fw[0], bw[0], zx_, B_ * L_, DIP, DM, DM, DM, DIP,
        0, 0, 0, 1, 0, SZ_ZX, L_, nullptr, nullptr);

    conv_silu_k<<<(int)((2LL * B_ * L_ * CD + 255) / 256), 256>>>(
        zx_, fw[1], fw[2], bw[1], bw[2], xbc_);
    dt_scan_k<<<2 * B_ * NH * NC, CH>>>(zx_, fw[3], fw[4], bw[3], bw[4], dt_, acs_);

    // CB = C @ B^T per (dir,b,c). A and B both come from xbc (per-dir); pass
    // xbc as both B0/B1 with dir handled by dA/dB via sB… B differs per dir:
    // use B0=xbc_+DI, B1=xbc_+SZ_XBC+DI and zz stride sB.
    gemm_tf32<128,64,0><<<dim3(CH / 64, CH / 128, 2 * B_ * NC), 256>>>(
        xbc_ + DI + DS, xbc_ + DI, xbc_ + SZ_XBC + DI, cb_, CH, CH, DS, CD, CD, CH,
        (long long)CH * CD, (long long)CH * CD, (long long)CH * CH,
        B_ * NC, SZ_XBC, SZ_CB, 0, nullptr, nullptr);

    states_mma_k<<<dim3(NH, NC, 2 * B_), 256>>>(xbc_, dt_, acs_, st_);
    chunkscan_k<<<(2 * B_ * NH * HD * DS) / 256, 256>>>(st_, acs_, pv_);
    ssd_y_mma_k<<<dim3(CH / 64, NH, 2 * B_ * NC), 256>>>(
        xbc_, dt_, acs_, cb_, pv_, fw[5], bw[5], y_);
    gate_rms_k<<<2 * B_ * L_, 256>>>(y_, zx_, fw[6], bw[6]);

    // out-projection, both dirs, fused epilogue into r (reversal + residual t)
    gemm_tf32<128,64,1><<<dim3(DM / 64, (B_ * L_) / 128, 2), 256>>>(
        y_, fw[7], bw[7], r_, B_ * L_, DM, DI, DI, DI, DM,
        0, 0, 0, 1, SZ_Y, 0, 0, t_, nullptr);

    // final projection, fused epilogue (transpose + x + bias)
    gemm_tf32<128,64,2><<<dim3(DM / 64, (B_ * L_) / 128, 1), 256>>>(
        r_, proj_w, proj_w, out, B_ * L_, DM, 2 * DM, 2 * DM, 2 * DM, DM,
        0, 0, 0, 1, 0, 0, 0, x, proj_b);
}

// round 6
// speedup vs baseline: 2.0489x; 1.1344x over previous
#include <cuda_runtime.h>
#include <cuda_bf16.h>
#include <math.h>
#include <stdint.h>

// ---------------- problem constants ----------------
static const int B_   = 2;
static const int L_   = 2048;
static const int DM   = 256;
static const int DS   = 128;
static const int DI   = 1024;
static const int NH   = 16;
static const int HD   = 64;
static const int CD   = 1280;
static const int DIP  = 2320;
static const int CH   = 256;
static const int NC   = 8;
#define GN_EPS 1.1920928955078125e-07f
#define RMS_EPS 1e-5f

#define SZ_ZX   ((long long)B_*L_*DIP)
#define SZ_XBC  ((long long)B_*L_*CD)
#define SZ_DT   ((long long)B_*L_*NH)
#define SZ_ACS  ((long long)B_*NH*L_)
#define SZ_CB   ((long long)B_*NC*CH*CH)
#define SZ_ST   ((long long)B_*NC*NH*HD*DS)
#define SZ_Y    ((long long)B_*L_*DI)

// ---------------- scratch ----------------
__device__ float g_t    [B_*L_*DM];
__device__ float g_zx   [2*B_*L_*DIP];
__device__ float g_xbc  [2*B_*L_*CD];
__device__ float g_dt   [2*B_*L_*NH];
__device__ float g_acs  [2*B_*NH*L_];
__device__ float g_cb   [2*B_*NC*CH*CH];
__device__ float g_st   [2*B_*NC*NH*HD*DS];
__device__ float g_pv   [2*B_*NC*NH*HD*DS];
__device__ float g_y    [2*B_*L_*DI];
__device__ float g_r    [B_*L_*2*DM];
__device__ float g_stats[4];

__device__ __forceinline__ float siluf(float x) { return x / (1.f + __expf(-x)); }
__device__ __forceinline__ float softplusf(float x) { return x > 20.f ? x : log1pf(expf(x)); }
__device__ __forceinline__ uint32_t f2tf32(float x) {
    uint32_t r; asm("cvt.rna.tf32.f32 %0, %1;" : "=r"(r) : "f"(x)); return r;
}
__device__ __forceinline__ float tf32v(float x) { return __uint_as_float(f2tf32(x)); }

#define MMA_TF32(acc, a, b) \
    asm volatile( \
        "mma.sync.aligned.m16n8k8.row.col.f32.tf32.tf32.f32 " \
        "{%0,%1,%2,%3},{%4,%5,%6,%7},{%8,%9},{%0,%1,%2,%3};" \
        : "+f"((acc)[0]), "+f"((acc)[1]), "+f"((acc)[2]), "+f"((acc)[3]) \
        : "r"((a)[0]), "r"((a)[1]), "r"((a)[2]), "r"((a)[3]), \
          "r"((b)[0]), "r"((b)[1]))

__device__ __forceinline__ void cpa16(uint32_t dst, const void* src, bool valid) {
    int sz = valid ? 16 : 0;
    asm volatile("cp.async.cg.shared.global [%0], [%1], 16, %2;\n"
                 :: "r"(dst), "l"(src), "r"(sz));
}
#define CPA_COMMIT() asm volatile("cp.async.commit_group;\n" ::)
#define CPA_WAIT1()  asm volatile("cp.async.wait_group 1;\n" ::)

// ---------------- GroupNorm stats ----------------
__global__ void gn_stats_k(const float* __restrict__ x, float* __restrict__ stats) {
    int b = blockIdx.x;
    const float* xb = x + (size_t)b * DM * L_;
    double s = 0.0, ss = 0.0;
    for (int i = threadIdx.x; i < DM * L_; i += blockDim.x) {
        double v = xb[i]; s += v; ss += v * v;
    }
    __shared__ double sh[512], sh2[512];
    sh[threadIdx.x] = s; sh2[threadIdx.x] = ss;
    __syncthreads();
    for (int o = 256; o > 0; o >>= 1) {
        if ((int)threadIdx.x < o) { sh[threadIdx.x] += sh[threadIdx.x + o]; sh2[threadIdx.x] += sh2[threadIdx.x + o]; }
        __syncthreads();
    }
    if (threadIdx.x == 0) {
        double n = (double)DM * L_;
        double mu = sh[0] / n;
        double var = sh2[0] / n - mu * mu;
        stats[b * 2 + 0] = (float)mu;
        stats[b * 2 + 1] = rsqrtf((float)var + GN_EPS);
    }
}

// ---------------- GroupNorm apply + transpose ----------------
__global__ void gn_apply_k(const float* __restrict__ x, const float* __restrict__ gw,
                           const float* __restrict__ gb, const float* __restrict__ stats,
                           float* __restrict__ t) {
    int b = blockIdx.z;
    __shared__ float tile[32][33];
    int l0 = blockIdx.x * 32, d0 = blockIdx.y * 32;
    float mu = stats[b * 2], rs = stats[b * 2 + 1];
#pragma unroll
    for (int r = 0; r < 4; r++) {
        int d = d0 + threadIdx.y + r * 8;
        tile[threadIdx.y + r * 8][threadIdx.x] = x[((size_t)b * DM + d) * L_ + l0 + threadIdx.x];
    }
    __syncthreads();
    int d = d0 + threadIdx.x;
    float w = gw[d], bb = gb[d];
#pragma unroll
    for (int r = 0; r < 4; r++) {
        int l = l0 + threadIdx.y + r * 8;
        t[((size_t)b * L_ + l) * DM + d] = (tile[threadIdx.x][threadIdx.y + r * 8] - mu) * rs * w + bb;
    }
}

// ---------------- TF32 tensor-core NT GEMM, cp.async 2-stage pipeline -------
// MODE 0: plain store. MODE 1: out-proj epilogue. MODE 2: final epilogue.
template<int BM, int BN, int MODE>
__global__ void __launch_bounds__(256)
gemm_tf32(const float* __restrict__ A, const float* __restrict__ B0,
          const float* __restrict__ B1, float* __restrict__ C,
          int M, int N, int K, int lda, int ldb, int ldc,
          long long sA, long long sB, long long sC,
          int zPerDir, long long dA, long long dC, int revL,
          const float* __restrict__ extra, const float* __restrict__ bias) {
    constexpr int BK = 32;
    constexpr int T  = 256;
    constexpr int LA = BM * BK / (T * 4);
    constexpr int LB = BN * BK / (T * 4);
    constexpr int MF = BM / 32;
    constexpr int NF = BN / 32;
    __shared__ float As[2][BM][BK + 4];
    __shared__ float Bs[2][BN][BK + 4];
    int z = blockIdx.z;
    int dir = z / zPerDir, zz = z % zPerDir;
    const float* Ap = A + dir * dA + zz * sA;
    const float* Bp = (dir ? B1 : B0) + zz * sB;
    float* Cp = C + dir * dC + zz * sC;
    int rev = dir ? revL : 0;
    int m0 = blockIdx.y * BM, n0 = blockIdx.x * BN;
    int tid = threadIdx.x;
    int warp = tid >> 5, lane = tid & 31;
    int wm = warp >> 2, wn = warp & 3;
    int group = lane >> 2, tig = lane & 3;
    float acc[MF][NF][4] = {};

    auto issue = [&](int k0, int s) {
#pragma unroll
        for (int i = 0; i < LA; i++) {
            int e = tid + i * T;
            int mm = e / (BK / 4);
            int kc = (e % (BK / 4)) * 4;
            int gm = m0 + mm;
            int row = gm < M ? gm : 0;
            if (rev && gm < M) { int bb = gm / rev; int ll = gm % rev; row = bb * rev + (rev - 1 - ll); }
            cpa16((uint32_t)__cvta_generic_to_shared(&As[s][mm][kc]),
                  Ap + (long long)row * lda + k0 + kc, gm < M);
        }
#pragma unroll
        for (int i = 0; i < LB; i++) {
            int e = tid + i * T;
            int nn = e / (BK / 4);
            int kc = (e % (BK / 4)) * 4;
            int gn = n0 + nn;
            int rowb = gn < N ? gn : 0;
            cpa16((uint32_t)__cvta_generic_to_shared(&Bs[s][nn][kc]),
                  Bp + (long long)rowb * ldb + k0 + kc, gn < N);
        }
    };
    auto compute = [&](int s) {
#pragma unroll
        for (int ks = 0; ks < BK / 8; ks++) {
            uint32_t af[MF][4], bf[NF][2];
#pragma unroll
            for (int mf = 0; mf < MF; mf++) {
                int rm = wm * (MF * 16) + mf * 16 + group;
                af[mf][0] = __float_as_uint(As[s][rm    ][ks * 8 + tig]);
                af[mf][1] = __float_as_uint(As[s][rm + 8][ks * 8 + tig]);
                af[mf][2] = __float_as_uint(As[s][rm    ][ks * 8 + tig + 4]);
                af[mf][3] = __float_as_uint(As[s][rm + 8][ks * 8 + tig + 4]);
            }
#pragma unroll
            for (int nf = 0; nf < NF; nf++) {
                int rn = wn * (NF * 8) + nf * 8 + group;
                bf[nf][0] = __float_as_uint(Bs[s][rn][ks * 8 + tig]);
                bf[nf][1] = __float_as_uint(Bs[s][rn][ks * 8 + tig + 4]);
            }
#pragma unroll
            for (int mf = 0; mf < MF; mf++)
#pragma unroll
                for (int nf = 0; nf < NF; nf++) MMA_TF32(acc[mf][nf], af[mf], bf[nf]);
        }
    };

    int nIter = K / BK;
    issue(0, 0);
    CPA_COMMIT();
    for (int it = 0; it < nIter; it++) {
        if (it + 1 < nIter) issue((it + 1) * BK, (it + 1) & 1);
        CPA_COMMIT();
        CPA_WAIT1();
        __syncthreads();
        compute(it & 1);
        __syncthreads();
    }

#pragma unroll
    for (int mf = 0; mf < MF; mf++) {
#pragma unroll
        for (int nf = 0; nf < NF; nf++) {
            int gn = n0 + wn * (NF * 8) + nf * 8 + 2 * tig;
#pragma unroll
            for (int rr = 0; rr < 2; rr++) {
                int gm = m0 + wm * (MF * 16) + mf * 16 + group + rr * 8;
                float a0 = acc[mf][nf][rr * 2 + 0], a1 = acc[mf][nf][rr * 2 + 1];
                if (MODE == 0) {
                    if (gm < M && gn < N)
                        *reinterpret_cast<float2*>(Cp + (long long)gm * ldc + gn) =
                            make_float2(a0, a1);
                } else if (MODE == 1) {
                    int b = gm / L_, l = gm % L_;
                    int ltm = dir ? (L_ - 1 - l) : l;
                    long long base = (long long)(b * L_ + ltm);
                    float2 tv = *reinterpret_cast<const float2*>(extra + base * DM + gn);
                    *reinterpret_cast<float2*>(C + base * (2 * DM) + dir * DM + gn) =
                        make_float2(a0 + tv.x, a1 + tv.y);
                } else {
                    int b = gm / L_, l = gm % L_;
                    long long i0 = ((long long)(b * DM + gn)) * L_ + l;
                    long long i1 = ((long long)(b * DM + gn + 1)) * L_ + l;
                    C[i0] = extra[i0] + bias[gn] + a0;
                    C[i1] = extra[i1] + bias[gn + 1] + a1;
                }
            }
        }
    }
}

// ---------------- depthwise conv + SiLU (dir-batched) ----------------
__global__ void conv_silu_k(const float* __restrict__ zx,
                            const float* __restrict__ cw0, const float* __restrict__ cb0,
                            const float* __restrict__ cw1, const float* __restrict__ cb1,
                            float* __restrict__ xbc) {
    long long idx = (long long)blockIdx.x * blockDim.x + threadIdx.x;
    if (idx >= 2LL * B_ * L_ * CD) return;
    int ch = idx % CD;
    int l  = (idx / CD) % L_;
    long long rest = idx / ((long long)CD * L_);
    int b = rest % B_;
    int dir = rest / B_;
    const float* cw = dir ? cw1 : cw0;
    const float* cb = dir ? cb1 : cb0;
    const float* zxd = zx + dir * SZ_ZX;
    float acc = cb[ch];
#pragma unroll
    for (int k = 0; k < 4; k++) {
        int lp = l - 3 + k;
        if (lp >= 0) acc += cw[ch * 4 + k] * zxd[(size_t)(b * L_ + lp) * DIP + DI + ch];
    }
    xbc[dir * SZ_XBC + ((size_t)(b * L_ + l)) * CD + ch] = siluf(acc);
}

// ---------------- dt softplus + per-chunk cumsum (dir-batched) ----------------
__global__ void dt_scan_k(const float* __restrict__ zx,
                          const float* __restrict__ db0, const float* __restrict__ al0,
                          const float* __restrict__ db1, const float* __restrict__ al1,
                          float* __restrict__ dt, float* __restrict__ acs) {
    int bi = blockIdx.x;
    int dir = bi / (B_ * NH * NC);
    bi %= B_ * NH * NC;
    int c = bi % NC, h = (bi / NC) % NH, b = bi / (NC * NH);
    const float* dt_bias = dir ? db1 : db0;
    const float* A_log   = dir ? al1 : al0;
    int l = threadIdx.x;
    int gl = c * CH + l;
    int row = b * L_ + gl;
    float v = zx[dir * SZ_ZX + (size_t)row * DIP + (DIP - NH) + h] + dt_bias[h];
    float dtv = softplusf(v);
    dt[dir * SZ_DT + (size_t)row * NH + h] = dtv;
    float a = -expf(A_log[h]) * dtv;
    __shared__ float sb[CH];
    sb[l] = a;
    __syncthreads();
    for (int off = 1; off < CH; off <<= 1) {
        float tv = (l >= off) ? sb[l - off] : 0.f;
        __syncthreads();
        sb[l] += tv;
        __syncthreads();
    }
    acs[dir * SZ_ACS + (size_t)(b * NH + h) * L_ + gl] = sb[l];
}

// ---------------- per-chunk end state via tf32 mma (dir-batched) ----------------
__global__ void __launch_bounds__(256)
states_mma_k(const float* __restrict__ xbc, const float* __restrict__ dt,
             const float* __restrict__ acs, float* __restrict__ st) {
    int h = blockIdx.x, c = blockIdx.y;
    int dir = blockIdx.z / B_, b = blockIdx.z % B_;
    const float* xbcd = xbc + dir * SZ_XBC;
    const float* dtd  = dt  + dir * SZ_DT;
    const float* acsd = acs + dir * SZ_ACS;
    int tid = threadIdx.x;
    int warp = tid >> 5, lane = tid & 31;
    int wm = warp >> 2, wn = warp & 3;
    int group = lane >> 2, tig = lane & 3;
    __shared__ float Xs[32][72];
    __shared__ float Bs[32][136];
    __shared__ float wrow[32];
    int acsbase = (b * NH + h) * L_ + c * CH;
    float csLast = acsd[acsbase + CH - 1];
    float acc[2][4][4] = {};
    for (int s0 = 0; s0 < CH; s0 += 32) {
        __syncthreads();
        if (tid < 32) {
            int row = b * L_ + c * CH + s0 + tid;
            wrow[tid] = dtd[(size_t)row * NH + h] * __expf(csLast - acsd[acsbase + s0 + tid]);
        }
        __syncthreads();
#pragma unroll
        for (int i = 0; i < 8; i++) {
            int e = tid + i * 256;
            int pp = e & 63, ss = e >> 6;
            int row = b * L_ + c * CH + s0 + ss;
            Xs[ss][pp] = tf32v(xbcd[(size_t)row * CD + h * HD + pp] * wrow[ss]);
        }
#pragma unroll
        for (int i = 0; i < 16; i++) {
            int e = tid + i * 256;
            int nn = e & 127, ss = e >> 7;
            int row = b * L_ + c * CH + s0 + ss;
            Bs[ss][nn] = tf32v(xbcd[(size_t)row * CD + DI + nn]);
        }
        __syncthreads();
#pragma unroll
        for (int ks = 0; ks < 4; ks++) {
            int k0 = ks * 8;
            uint32_t af[2][4], bf[4][2];
#pragma unroll
            for (int mf = 0; mf < 2; mf++) {
                int rm = wm * 32 + mf * 16 + group;
                af[mf][0] = __float_as_uint(Xs[k0 + tig    ][rm]);
                af[mf][1] = __float_as_uint(Xs[k0 + tig    ][rm + 8]);
                af[mf][2] = __float_as_uint(Xs[k0 + tig + 4][rm]);
                af[mf][3] = __float_as_uint(Xs[k0 + tig + 4][rm + 8]);
            }
#pragma unroll
            for (int nf = 0; nf < 4; nf++) {
                int rn = wn * 32 + nf * 8 + group;
                bf[nf][0] = __float_as_uint(Bs[k0 + tig    ][rn]);
                bf[nf][1] = __float_as_uint(Bs[k0 + tig + 4][rn]);
            }
#pragma unroll
            for (int mf = 0; mf < 2; mf++)
#pragma unroll
                for (int nf = 0; nf < 4; nf++) MMA_TF32(acc[mf][nf], af[mf], bf[nf]);
        }
    }
    float* base = st + dir * SZ_ST + (size_t)((b * NC + c) * NH + h) * HD * DS;
#pragma unroll
    for (int mf = 0; mf < 2; mf++) {
#pragma unroll
        for (int nf = 0; nf < 4; nf++) {
            int gm = wm * 32 + mf * 16 + group;
            int gn = wn * 32 + nf * 8 + 2 * tig;
            *reinterpret_cast<float2*>(base + gm * DS + gn) =
                make_float2(acc[mf][nf][0], acc[mf][nf][1]);
            *reinterpret_cast<float2*>(base + (gm + 8) * DS + gn) =
                make_float2(acc[mf][nf][2], acc[mf][nf][3]);
        }
    }
}

// ---------------- inter-chunk recurrence (dir-batched) ----------------
__global__ void chunkscan_k(const float* __restrict__ st, const float* __restrict__ acs,
                            float* __restrict__ pv) {
    int idx = blockIdx.x * blockDim.x + threadIdx.x;
    int n = idx & (DS - 1);
    int p = (idx >> 7) & (HD - 1);
    int h = (idx >> 13) & (NH - 1);
    int b = (idx >> 17) & (B_ - 1);
    int dir = idx >> 18;
    const float* std_ = st + dir * SZ_ST;
    const float* acsd = acs + dir * SZ_ACS;
    float* pvd = pv + dir * SZ_ST;
    float S = 0.f;
    for (int c = 0; c < NC; c++) {
        size_t off = ((size_t)((b * NC + c) * NH + h) * HD + p) * DS + n;
        pvd[off] = S;
        float at = acsd[(b * NH + h) * L_ + c * CH + CH - 1];
        S = S * expf(at) + std_[off];
    }
}

// ---------------- Y via tf32 mma, factorized decay exp (dir-batched) --------
__global__ void __launch_bounds__(256)
ssd_y_mma_k(const float* __restrict__ xbc, const float* __restrict__ dt,
            const float* __restrict__ acs, const float* __restrict__ cb,
            const float* __restrict__ pv,
            const float* __restrict__ Dh0, const float* __restrict__ Dh1,
            float* __restrict__ y) {
    int lt = blockIdx.x, h = blockIdx.y;
    int dir = blockIdx.z / (B_ * NC);
    int bc = blockIdx.z % (B_ * NC);
    int c = bc % NC, b = bc / NC;
    const float* xbcd = xbc + dir * SZ_XBC;
    const float* dtd  = dt  + dir * SZ_DT;
    const float* acsd = acs + dir * SZ_ACS;
    const float* Dh   = dir ? Dh1 : Dh0;
    int tid = threadIdx.x;
    int warp = tid >> 5, lane = tid & 31;
    int wm = warp >> 2, wn = warp & 3;
    int group = lane >> 2, tig = lane & 3;
    __shared__ float Ws[64][36];
    __shared__ float Xs[32][72];
    __shared__ float Ps[64][36];
    __shared__ float csl[64], css[32], einv[32];
    __shared__ float el64[64];  // exp(csl[ii]-csl0)
    __shared__ float eoff[64];  // exp(csl[ii])
    int l0 = lt * 64;
    int acsbase = (b * NH + h) * L_ + c * CH;
    if (tid < 64) {
        float v = acsd[acsbase + l0 + tid];
        float v0 = acsd[acsbase + l0];
        csl[tid]  = v;
        el64[tid] = __expf(v - v0);
        eoff[tid] = __expf(v);
    }
    const float* cbb = cb + dir * SZ_CB + (size_t)(b * NC + c) * CH * CH;
    float acc[2][2][4] = {};
    int nst = 2 * lt + 2;
    for (int stp = 0; stp < nst; stp++) {
        int s0 = stp * 32;
        bool lower = (s0 + 31 < l0);   // strictly below diagonal
        __syncthreads();
        if (tid < 32) {
            float cv = acsd[acsbase + s0 + tid];
            css[tid] = cv;
            einv[tid] = __expf(csl[0] - cv);   // csl[0] valid after prior sync
        }
        __syncthreads();
        if (lower) {
#pragma unroll
            for (int i = 0; i < 8; i++) {
                int e = tid + i * 256;
                int j = e & 31, ii = e >> 5;
                Ws[ii][j] = tf32v(el64[ii] * einv[j] * cbb[(l0 + ii) * CH + s0 + j]);
            }
        } else {
#pragma unroll
            for (int i = 0; i < 8; i++) {
                int e = tid + i * 256;
                int j = e & 31, ii = e >> 5;
                float w = 0.f;
                if (s0 + j <= l0 + ii) w = __expf(csl[ii] - css[j]) * cbb[(l0 + ii) * CH + s0 + j];
                Ws[ii][j] = tf32v(w);
            }
        }
#pragma unroll
        for (int i = 0; i < 8; i++) {
            int e = tid + i * 256;
            int pp = e & 63, ss = e >> 6;
            int row = b * L_ + c * CH + s0 + ss;
            Xs[ss][pp] = tf32v(xbcd[(size_t)row * CD + h * HD + pp] * dtd[(size_t)row * NH + h]);
        }
        __syncthreads();
#pragma unroll
        for (int ks = 0; ks < 4; ks++) {
            int k0 = ks * 8;
            uint32_t af[2][4], bf[2][2];
#pragma unroll
            for (int mf = 0; mf < 2; mf++) {
                int rm = wm * 32 + mf * 16 + group;
                af[mf][0] = __float_as_uint(Ws[rm    ][k0 + tig]);
                af[mf][1] = __float_as_uint(Ws[rm + 8][k0 + tig]);
                af[mf][2] = __float_as_uint(Ws[rm    ][k0 + tig + 4]);
                af[mf][3] = __float_as_uint(Ws[rm + 8][k0 + tig + 4]);
            }
#pragma unroll
            for (int nf = 0; nf < 2; nf++) {
                int rn = wn * 16 + nf * 8 + group;
                bf[nf][0] = __float_as_uint(Xs[k0 + tig    ][rn]);
                bf[nf][1] = __float_as_uint(Xs[k0 + tig + 4][rn]);
            }
#pragma unroll
            for (int mf = 0; mf < 2; mf++)
#pragma unroll
                for (int nf = 0; nf < 2; nf++) MMA_TF32(acc[mf][nf], af[mf], bf[nf]);
        }
    }
    const float* pvb = pv + dir * SZ_ST + (size_t)((b * NC + c) * NH + h) * HD * DS;
    for (int nt = 0; nt < 4; nt++) {
        int n0 = nt * 32;
        __syncthreads();
#pragma unroll
        for (int i = 0; i < 8; i++) {
            int e = tid + i * 256;
            int j = e & 31, ii = e >> 5;
            int row = b * L_ + c * CH + l0 + ii;
            Ws[ii][j] = tf32v(xbcd[(size_t)row * CD + DI + DS + n0 + j] * eoff[ii]);
        }
#pragma unroll
        for (int i = 0; i < 8; i++) {
            int e = tid + i * 256;
            int j = e & 31, pp = e >> 5;
            Ps[pp][j] = tf32v(pvb[pp * DS + n0 + j]);
        }
        __syncthreads();
#pragma unroll
        for (int ks = 0; ks < 4; ks++) {
            int k0 = ks * 8;
            uint32_t af[2][4], bf[2][2];
#pragma unroll
            for (int mf = 0; mf < 2; mf++) {
                int rm = wm * 32 + mf * 16 + group;
                af[mf][0] = __float_as_uint(Ws[rm    ][k0 + tig]);
                af[mf][1] = __float_as_uint(Ws[rm + 8][k0 + tig]);
                af[mf][2] = __float_as_uint(Ws[rm    ][k0 + tig + 4]);
                af[mf][3] = __float_as_uint(Ws[rm + 8][k0 + tig + 4]);
            }
#pragma unroll
            for (int nf = 0; nf < 2; nf++) {
                int rn = wn * 16 + nf * 8 + group;
                bf[nf][0] = __float_as_uint(Ps[rn][k0 + tig]);
                bf[nf][1] = __float_as_uint(Ps[rn][k0 + tig + 4]);
            }
#pragma unroll
            for (int mf = 0; mf < 2; mf++)
#pragma unroll
                for (int nf = 0; nf < 2; nf++) MMA_TF32(acc[mf][nf], af[mf], bf[nf]);
        }
    }
    float dh = Dh[h];
    float* yd = y + dir * SZ_Y;
#pragma unroll
    for (int mf = 0; mf < 2; mf++) {
#pragma unroll
        for (int nf = 0; nf < 2; nf++) {
            int ll = l0 + wm * 32 + mf * 16 + group;
            int pp = wn * 16 + nf * 8 + 2 * tig;
#pragma unroll
            for (int rr = 0; rr < 2; rr++) {
                int row = b * L_ + c * CH + ll + rr * 8;
                float2 xr = *reinterpret_cast<const float2*>(
                    xbcd + (size_t)row * CD + h * HD + pp);
                *reinterpret_cast<float2*>(yd + (size_t)row * DI + h * HD + pp) =
                    make_float2(acc[mf][nf][rr * 2 + 0] + xr.x * dh,
                                acc[mf][nf][rr * 2 + 1] + xr.y * dh);
            }
        }
    }
}

// ---------------- gating + RMSNorm (dir-batched) ----------------
__global__ void gate_rms_k(float* __restrict__ y, const float* __restrict__ zx,
                           const float* __restrict__ nw0, const float* __restrict__ nw1) {
    int row = blockIdx.x;
    int dir = row / (B_ * L_);
    row %= B_ * L_;
    const float* nw = dir ? nw1 : nw0;
    float* yd = y + dir * SZ_Y;
    const float* zxd = zx + dir * SZ_ZX;
    int tid = threadIdx.x;
    float v[4];
    float ss = 0.f;
#pragma unroll
    for (int i = 0; i < 4; i++) {
        int d = i * 256 + tid;
        float z = zxd[(size_t)row * DIP + d];
        float yy = yd[(size_t)row * DI + d] * siluf(z);
        v[i] = yy;
        ss += yy * yy;
    }
    __shared__ float sh[256];
    sh[tid] = ss;
    __syncthreads();
    for (int o = 128; o > 0; o >>= 1) {
        if (tid < o) sh[tid] += sh[tid + o];
        __syncthreads();
    }
    float scale = rsqrtf(sh[0] / DI + RMS_EPS);
#pragma unroll
    for (int i = 0; i < 4; i++) {
        int d = i * 256 + tid;
        yd[(size_t)row * DI + d] = v[i] * scale * nw[d];
    }
}

// ---------------- launch ----------------
extern "C" void kernel_launch(void* const* d_in, const int* in_sizes, int n_in,
                              void* d_out, int out_size) {
    (void)in_sizes; (void)n_in; (void)out_size;
    const float* x      = (const float*)d_in[0];
    const float* gn_w   = (const float*)d_in[1];
    const float* gn_b   = (const float*)d_in[2];
    const float* proj_w = (const float*)d_in[3];
    const float* proj_b = (const float*)d_in[4];
    const float* fw[8], *bw[8];
    for (int i = 0; i < 8; i++) { fw[i] = (const float*)d_in[5 + i]; bw[i] = (const float*)d_in[13 + i]; }
    float* out = (float*)d_out;

    float *t_, *zx_, *xbc_, *dt_, *acs_, *cb_, *st_, *pv_, *y_, *r_, *stats_;
    cudaGetSymbolAddress((void**)&t_,    g_t);
    cudaGetSymbolAddress((void**)&zx_,   g_zx);
    cudaGetSymbolAddress((void**)&xbc_,  g_xbc);
    cudaGetSymbolAddress((void**)&dt_,   g_dt);
    cudaGetSymbolAddress((void**)&acs_,  g_acs);
    cudaGetSymbolAddress((void**)&cb_,   g_cb);
    cudaGetSymbolAddress((void**)&st_,   g_st);
    cudaGetSymbolAddress((void**)&pv_,   g_pv);
    cudaGetSymbolAddress((void**)&y_,    g_y);
    cudaGetSymbolAddress((void**)&r_,    g_r);
    cudaGetSymbolAddress((void**)&stats_,g_stats);

    gn_stats_k<<<B_, 512>>>(x, stats_);
    gn_apply_k<<<dim3(L_ / 32, DM / 32, B_), dim3(32, 8)>>>(x, gn_w, gn_b, stats_, t_);

    gemm_tf32<128,128,0><<<dim3((DIP + 127) / 128, (B_ * L_) / 128, 2), 256>>>(
        t_, fw[0], bw[0], zx_, B_ * L_, DIP, DM, DM, DM, DIP,
        0, 0, 0, 1, 0, SZ_ZX, L_, nullptr, nullptr);

    conv_silu_k<<<(int)((2LL * B_ * L_ * CD + 255) / 256), 256>>>(
        zx_, fw[1], fw[2], bw[1], bw[2], xbc_);
    dt_scan_k<<<2 * B_ * NH * NC, CH>>>(zx_, fw[3], fw[4], bw[3], bw[4], dt_, acs_);

    gemm_tf32<128,64,0><<<dim3(CH / 64, CH / 128, 2 * B_ * NC), 256>>>(
        xbc_ + DI + DS, xbc_ + DI, xbc_ + SZ_XBC + DI, cb_, CH, CH, DS, CD, CD, CH,
        (long long)CH * CD, (long long)CH * CD, (long long)CH * CH,
        B_ * NC, SZ_XBC, SZ_CB, 0, nullptr, nullptr);

    states_mma_k<<<dim3(NH, NC, 2 * B_), 256>>>(xbc_, dt_, acs_, st_);
    chunkscan_k<<<(2 * B_ * NH * HD * DS) / 256, 256>>>(st_, acs_, pv_);
    ssd_y_mma_k<<<dim3(CH / 64, NH, 2 * B_ * NC), 256>>>(
        xbc_, dt_, acs_, cb_, pv_, fw[5], bw[5], y_);
    gate_rms_k<<<2 * B_ * L_, 256>>>(y_, zx_, fw[6], bw[6]);

    gemm_tf32<128,64,1><<<dim3(DM / 64, (B_ * L_) / 128, 2), 256>>>(
        y_, fw[7], bw[7], r_, B_ * L_, DM, DI, DI, DI, DM,
        0, 0, 0, 1, SZ_Y, 0, 0, t_, nullptr);

    gemm_tf32<128,64,2><<<dim3(DM / 64, (B_ * L_) / 128, 1), 256>>>(
        r_, proj_w, proj_w, out, B_ * L_, DM, 2 * DM, 2 * DM, 2 * DM, DM,
        0, 0, 0, 1, 0, 0, 0, x, proj_b);
}

// round 7
// speedup vs baseline: 4.1381x; 2.0197x over previous
#include <cuda_runtime.h>
#include <cuda_bf16.h>
#include <math.h>
#include <stdint.h>

// ---------------- problem constants ----------------
static const int B_   = 2;
static const int L_   = 2048;
static const int DM   = 256;
static const int DS   = 128;
static const int DI   = 1024;
static const int NH   = 16;
static const int HD   = 64;
static const int CD   = 1280;
static const int DIP  = 2320;
static const int CH   = 256;
static const int NC   = 8;
#define GN_EPS 1.1920928955078125e-07f
#define RMS_EPS 1e-5f

#define SZ_ZX   ((long long)B_*L_*DIP)
#define SZ_XBC  ((long long)B_*L_*CD)
#define SZ_DT   ((long long)B_*L_*NH)
#define SZ_ACS  ((long long)B_*NH*L_)
#define SZ_CB   ((long long)B_*NC*CH*CH)
#define SZ_ST   ((long long)B_*NC*NH*HD*DS)
#define SZ_Y    ((long long)B_*L_*DI)

// ---------------- scratch ----------------
__device__ float g_t    [B_*L_*DM];
__device__ float g_zx   [2*B_*L_*DIP];
__device__ float g_xbc  [2*B_*L_*CD];
__device__ float g_dt   [2*B_*L_*NH];
__device__ float g_acs  [2*B_*NH*L_];
__device__ float g_cb   [2*B_*NC*CH*CH];
__device__ float g_st   [2*B_*NC*NH*HD*DS];
__device__ float g_pv   [2*B_*NC*NH*HD*DS];
__device__ float g_y    [2*B_*L_*DI];
__device__ float g_r    [B_*L_*2*DM];
__device__ float g_part [B_*64*2];
__device__ float g_stats[4];

__device__ __forceinline__ float siluf(float x) { return x / (1.f + __expf(-x)); }
__device__ __forceinline__ float softplusf(float x) { return x > 20.f ? x : log1pf(expf(x)); }
__device__ __forceinline__ uint32_t f2tf32(float x) {
    uint32_t r; asm("cvt.rna.tf32.f32 %0, %1;" : "=r"(r) : "f"(x)); return r;
}
__device__ __forceinline__ float tf32v(float x) { return __uint_as_float(f2tf32(x)); }

#define MMA_TF32(acc, a, b) \
    asm volatile( \
        "mma.sync.aligned.m16n8k8.row.col.f32.tf32.tf32.f32 " \
        "{%0,%1,%2,%3},{%4,%5,%6,%7},{%8,%9},{%0,%1,%2,%3};" \
        : "+f"((acc)[0]), "+f"((acc)[1]), "+f"((acc)[2]), "+f"((acc)[3]) \
        : "r"((a)[0]), "r"((a)[1]), "r"((a)[2]), "r"((a)[3]), \
          "r"((b)[0]), "r"((b)[1]))

__device__ __forceinline__ void cpa16(uint32_t dst, const void* src, bool valid) {
    int sz = valid ? 16 : 0;
    asm volatile("cp.async.cg.shared.global [%0], [%1], 16, %2;\n"
                 :: "r"(dst), "l"(src), "r"(sz));
}
#define CPA_COMMIT() asm volatile("cp.async.commit_group;\n" ::)
#define CPA_WAIT1()  asm volatile("cp.async.wait_group 1;\n" ::)

// ---------------- GroupNorm stats: stage 1 (64 blocks/batch, fp32) ----------
__global__ void gn_part_k(const float* __restrict__ x, float* __restrict__ part) {
    int b = blockIdx.y;
    const float* xb = x + (size_t)b * DM * L_;
    float s = 0.f, ss = 0.f;
    for (int i = blockIdx.x * blockDim.x + threadIdx.x; i < DM * L_; i += 64 * 256) {
        float v = xb[i]; s += v; ss += v * v;
    }
    __shared__ float sh[256], sh2[256];
    sh[threadIdx.x] = s; sh2[threadIdx.x] = ss;
    __syncthreads();
    for (int o = 128; o > 0; o >>= 1) {
        if ((int)threadIdx.x < o) { sh[threadIdx.x] += sh[threadIdx.x + o]; sh2[threadIdx.x] += sh2[threadIdx.x + o]; }
        __syncthreads();
    }
    if (threadIdx.x == 0) {
        part[(b * 64 + blockIdx.x) * 2 + 0] = sh[0];
        part[(b * 64 + blockIdx.x) * 2 + 1] = sh2[0];
    }
}

// ---------------- GroupNorm stats: stage 2 (1 block/batch) ----------------
__global__ void gn_fin_k(const float* __restrict__ part, float* __restrict__ stats) {
    int b = blockIdx.x;
    __shared__ double sh[64], sh2[64];
    int i = threadIdx.x;
    sh[i]  = (double)part[(b * 64 + i) * 2 + 0];
    sh2[i] = (double)part[(b * 64 + i) * 2 + 1];
    __syncthreads();
    for (int o = 32; o > 0; o >>= 1) {
        if (i < o) { sh[i] += sh[i + o]; sh2[i] += sh2[i + o]; }
        __syncthreads();
    }
    if (i == 0) {
        double n = (double)DM * L_;
        double mu = sh[0] / n;
        double var = sh2[0] / n - mu * mu;
        stats[b * 2 + 0] = (float)mu;
        stats[b * 2 + 1] = rsqrtf((float)var + GN_EPS);
    }
}

// ---------------- GroupNorm apply + transpose ----------------
__global__ void gn_apply_k(const float* __restrict__ x, const float* __restrict__ gw,
                           const float* __restrict__ gb, const float* __restrict__ stats,
                           float* __restrict__ t) {
    int b = blockIdx.z;
    __shared__ float tile[32][33];
    int l0 = blockIdx.x * 32, d0 = blockIdx.y * 32;
    float mu = stats[b * 2], rs = stats[b * 2 + 1];
#pragma unroll
    for (int r = 0; r < 4; r++) {
        int d = d0 + threadIdx.y + r * 8;
        tile[threadIdx.y + r * 8][threadIdx.x] = x[((size_t)b * DM + d) * L_ + l0 + threadIdx.x];
    }
    __syncthreads();
    int d = d0 + threadIdx.x;
    float w = gw[d], bb = gb[d];
#pragma unroll
    for (int r = 0; r < 4; r++) {
        int l = l0 + threadIdx.y + r * 8;
        t[((size_t)b * L_ + l) * DM + d] = (tile[threadIdx.x][threadIdx.y + r * 8] - mu) * rs * w + bb;
    }
}

// ---------------- TF32 tensor-core NT GEMM, cp.async 2-stage pipeline -------
template<int BM, int BN, int MODE>
__global__ void __launch_bounds__(256)
gemm_tf32(const float* __restrict__ A, const float* __restrict__ B0,
          const float* __restrict__ B1, float* __restrict__ C,
          int M, int N, int K, int lda, int ldb, int ldc,
          long long sA, long long sB, long long sC,
          int zPerDir, long long dA, long long dC, int revL,
          const float* __restrict__ extra, const float* __restrict__ bias) {
    constexpr int BK = 32;
    constexpr int T  = 256;
    constexpr int LA = BM * BK / (T * 4);
    constexpr int LB = BN * BK / (T * 4);
    constexpr int MF = BM / 32;
    constexpr int NF = BN / 32;
    __shared__ float As[2][BM][BK + 4];
    __shared__ float Bs[2][BN][BK + 4];
    int z = blockIdx.z;
    int dir = z / zPerDir, zz = z % zPerDir;
    const float* Ap = A + dir * dA + zz * sA;
    const float* Bp = (dir ? B1 : B0) + zz * sB;
    float* Cp = C + dir * dC + zz * sC;
    int rev = dir ? revL : 0;
    int m0 = blockIdx.y * BM, n0 = blockIdx.x * BN;
    int tid = threadIdx.x;
    int warp = tid >> 5, lane = tid & 31;
    int wm = warp >> 2, wn = warp & 3;
    int group = lane >> 2, tig = lane & 3;
    float acc[MF][NF][4] = {};

    auto issue = [&](int k0, int s) {
#pragma unroll
        for (int i = 0; i < LA; i++) {
            int e = tid + i * T;
            int mm = e / (BK / 4);
            int kc = (e % (BK / 4)) * 4;
            int gm = m0 + mm;
            int row = gm < M ? gm : 0;
            if (rev && gm < M) { int bb = gm / rev; int ll = gm % rev; row = bb * rev + (rev - 1 - ll); }
            cpa16((uint32_t)__cvta_generic_to_shared(&As[s][mm][kc]),
                  Ap + (long long)row * lda + k0 + kc, gm < M);
        }
#pragma unroll
        for (int i = 0; i < LB; i++) {
            int e = tid + i * T;
            int nn = e / (BK / 4);
            int kc = (e % (BK / 4)) * 4;
            int gn = n0 + nn;
            int rowb = gn < N ? gn : 0;
            cpa16((uint32_t)__cvta_generic_to_shared(&Bs[s][nn][kc]),
                  Bp + (long long)rowb * ldb + k0 + kc, gn < N);
        }
    };
    auto compute = [&](int s) {
#pragma unroll
        for (int ks = 0; ks < BK / 8; ks++) {
            uint32_t af[MF][4], bf[NF][2];
#pragma unroll
            for (int mf = 0; mf < MF; mf++) {
                int rm = wm * (MF * 16) + mf * 16 + group;
                af[mf][0] = __float_as_uint(As[s][rm    ][ks * 8 + tig]);
                af[mf][1] = __float_as_uint(As[s][rm + 8][ks * 8 + tig]);
                af[mf][2] = __float_as_uint(As[s][rm    ][ks * 8 + tig + 4]);
                af[mf][3] = __float_as_uint(As[s][rm + 8][ks * 8 + tig + 4]);
            }
#pragma unroll
            for (int nf = 0; nf < NF; nf++) {
                int rn = wn * (NF * 8) + nf * 8 + group;
                bf[nf][0] = __float_as_uint(Bs[s][rn][ks * 8 + tig]);
                bf[nf][1] = __float_as_uint(Bs[s][rn][ks * 8 + tig + 4]);
            }
#pragma unroll
            for (int mf = 0; mf < MF; mf++)
#pragma unroll
                for (int nf = 0; nf < NF; nf++) MMA_TF32(acc[mf][nf], af[mf], bf[nf]);
        }
    };

    int nIter = K / BK;
    issue(0, 0);
    CPA_COMMIT();
    for (int it = 0; it < nIter; it++) {
        if (it + 1 < nIter) issue((it + 1) * BK, (it + 1) & 1);
        CPA_COMMIT();
        CPA_WAIT1();
        __syncthreads();
        compute(it & 1);
        __syncthreads();
    }

#pragma unroll
    for (int mf = 0; mf < MF; mf++) {
#pragma unroll
        for (int nf = 0; nf < NF; nf++) {
            int gn = n0 + wn * (NF * 8) + nf * 8 + 2 * tig;
#pragma unroll
            for (int rr = 0; rr < 2; rr++) {
                int gm = m0 + wm * (MF * 16) + mf * 16 + group + rr * 8;
                float a0 = acc[mf][nf][rr * 2 + 0], a1 = acc[mf][nf][rr * 2 + 1];
                if (MODE == 0) {
                    if (gm < M && gn < N)
                        *reinterpret_cast<float2*>(Cp + (long long)gm * ldc + gn) =
                            make_float2(a0, a1);
                } else if (MODE == 1) {
                    int b = gm / L_, l = gm % L_;
                    int ltm = dir ? (L_ - 1 - l) : l;
                    long long base = (long long)(b * L_ + ltm);
                    float2 tv = *reinterpret_cast<const float2*>(extra + base * DM + gn);
                    *reinterpret_cast<float2*>(C + base * (2 * DM) + dir * DM + gn) =
                        make_float2(a0 + tv.x, a1 + tv.y);
                } else {
                    int b = gm / L_, l = gm % L_;
                    long long i0 = ((long long)(b * DM + gn)) * L_ + l;
                    long long i1 = ((long long)(b * DM + gn + 1)) * L_ + l;
                    C[i0] = extra[i0] + bias[gn] + a0;
                    C[i1] = extra[i1] + bias[gn + 1] + a1;
                }
            }
        }
    }
}

// ---------------- depthwise conv + SiLU (float4 over channels) --------------
__global__ void conv_silu_k(const float* __restrict__ zx,
                            const float* __restrict__ cw0, const float* __restrict__ cb0,
                            const float* __restrict__ cw1, const float* __restrict__ cb1,
                            float* __restrict__ xbc) {
    long long idx = (long long)blockIdx.x * blockDim.x + threadIdx.x; // over CD/4 groups
    if (idx >= 2LL * B_ * L_ * (CD / 4)) return;
    int cg = idx % (CD / 4);
    int l  = (idx / (CD / 4)) % L_;
    long long rest = idx / ((long long)(CD / 4) * L_);
    int b = rest % B_;
    int dir = rest / B_;
    const float* cw = (dir ? cw1 : cw0) + cg * 16;
    const float* cb = (dir ? cb1 : cb0) + cg * 4;
    const float* zxd = zx + dir * SZ_ZX + (size_t)(b * L_) * DIP + DI + cg * 4;
    float4 w0 = *reinterpret_cast<const float4*>(cw);       // taps ch0
    float4 w1 = *reinterpret_cast<const float4*>(cw + 4);   // taps ch1
    float4 w2 = *reinterpret_cast<const float4*>(cw + 8);
    float4 w3 = *reinterpret_cast<const float4*>(cw + 12);
    float4 acc = *reinterpret_cast<const float4*>(cb);
#pragma unroll
    for (int k = 0; k < 4; k++) {
        int lp = l - 3 + k;
        if (lp >= 0) {
            float4 v = *reinterpret_cast<const float4*>(zxd + (size_t)lp * DIP);
            acc.x += ((const float*)&w0)[k] * v.x;
            acc.y += ((const float*)&w1)[k] * v.y;
            acc.z += ((const float*)&w2)[k] * v.z;
            acc.w += ((const float*)&w3)[k] * v.w;
        }
    }
    acc.x = siluf(acc.x); acc.y = siluf(acc.y); acc.z = siluf(acc.z); acc.w = siluf(acc.w);
    *reinterpret_cast<float4*>(xbc + dir * SZ_XBC + ((size_t)(b * L_ + l)) * CD + cg * 4) = acc;
}

// ---------------- dt softplus + per-chunk cumsum (shuffle scan) -------------
__global__ void dt_scan_k(const float* __restrict__ zx,
                          const float* __restrict__ db0, const float* __restrict__ al0,
                          const float* __restrict__ db1, const float* __restrict__ al1,
                          float* __restrict__ dt, float* __restrict__ acs) {
    int bi = blockIdx.x;
    int dir = bi / (B_ * NH * NC);
    bi %= B_ * NH * NC;
    int c = bi % NC, h = (bi / NC) % NH, b = bi / (NC * NH);
    const float* dt_bias = dir ? db1 : db0;
    const float* A_log   = dir ? al1 : al0;
    int l = threadIdx.x;
    int lane = l & 31, warp = l >> 5;
    int gl = c * CH + l;
    int row = b * L_ + gl;
    float v = zx[dir * SZ_ZX + (size_t)row * DIP + (DIP - NH) + h] + dt_bias[h];
    float dtv = softplusf(v);
    dt[dir * SZ_DT + (size_t)row * NH + h] = dtv;
    float a = -expf(A_log[h]) * dtv;
#pragma unroll
    for (int o = 1; o < 32; o <<= 1) {
        float t = __shfl_up_sync(0xffffffff, a, o);
        if (lane >= o) a += t;
    }
    __shared__ float wsum[8];
    if (lane == 31) wsum[warp] = a;
    __syncthreads();
    float off = 0.f;
#pragma unroll
    for (int w = 0; w < 8; w++) if (w < warp) off += wsum[w];
    acs[dir * SZ_ACS + (size_t)(b * NH + h) * L_ + gl] = a + off;
}

// ---------------- per-chunk end state via tf32 mma ----------------
__global__ void __launch_bounds__(256)
states_mma_k(const float* __restrict__ xbc, const float* __restrict__ dt,
             const float* __restrict__ acs, float* __restrict__ st) {
    int h = blockIdx.x, c = blockIdx.y;
    int dir = blockIdx.z / B_, b = blockIdx.z % B_;
    const float* xbcd = xbc + dir * SZ_XBC;
    const float* dtd  = dt  + dir * SZ_DT;
    const float* acsd = acs + dir * SZ_ACS;
    int tid = threadIdx.x;
    int warp = tid >> 5, lane = tid & 31;
    int wm = warp >> 2, wn = warp & 3;
    int group = lane >> 2, tig = lane & 3;
    __shared__ float Xs[32][72];
    __shared__ float Bs[32][136];
    __shared__ float wrow[CH];
    int acsbase = (b * NH + h) * L_ + c * CH;
    float csLast = acsd[acsbase + CH - 1];
    {
        int row = b * L_ + c * CH + tid;
        wrow[tid] = dtd[(size_t)row * NH + h] * __expf(csLast - acsd[acsbase + tid]);
    }
    __syncthreads();
    float acc[2][4][4] = {};
    for (int s0 = 0; s0 < CH; s0 += 32) {
#pragma unroll
        for (int i = 0; i < 8; i++) {
            int e = tid + i * 256;
            int pp = e & 63, ss = e >> 6;
            int row = b * L_ + c * CH + s0 + ss;
            Xs[ss][pp] = tf32v(xbcd[(size_t)row * CD + h * HD + pp] * wrow[s0 + ss]);
        }
#pragma unroll
        for (int i = 0; i < 16; i++) {
            int e = tid + i * 256;
            int nn = e & 127, ss = e >> 7;
            int row = b * L_ + c * CH + s0 + ss;
            Bs[ss][nn] = tf32v(xbcd[(size_t)row * CD + DI + nn]);
        }
        __syncthreads();
#pragma unroll
        for (int ks = 0; ks < 4; ks++) {
            int k0 = ks * 8;
            uint32_t af[2][4], bf[4][2];
#pragma unroll
            for (int mf = 0; mf < 2; mf++) {
                int rm = wm * 32 + mf * 16 + group;
                af[mf][0] = __float_as_uint(Xs[k0 + tig    ][rm]);
                af[mf][1] = __float_as_uint(Xs[k0 + tig    ][rm + 8]);
                af[mf][2] = __float_as_uint(Xs[k0 + tig + 4][rm]);
                af[mf][3] = __float_as_uint(Xs[k0 + tig + 4][rm + 8]);
            }
#pragma unroll
            for (int nf = 0; nf < 4; nf++) {
                int rn = wn * 32 + nf * 8 + group;
                bf[nf][0] = __float_as_uint(Bs[k0 + tig    ][rn]);
                bf[nf][1] = __float_as_uint(Bs[k0 + tig + 4][rn]);
            }
#pragma unroll
            for (int mf = 0; mf < 2; mf++)
#pragma unroll
                for (int nf = 0; nf < 4; nf++) MMA_TF32(acc[mf][nf], af[mf], bf[nf]);
        }
        __syncthreads();
    }
    float* base = st + dir * SZ_ST + (size_t)((b * NC + c) * NH + h) * HD * DS;
#pragma unroll
    for (int mf = 0; mf < 2; mf++) {
#pragma unroll
        for (int nf = 0; nf < 4; nf++) {
            int gm = wm * 32 + mf * 16 + group;
            int gn = wn * 32 + nf * 8 + 2 * tig;
            *reinterpret_cast<float2*>(base + gm * DS + gn) =
                make_float2(acc[mf][nf][0], acc[mf][nf][1]);
            *reinterpret_cast<float2*>(base + (gm + 8) * DS + gn) =
                make_float2(acc[mf][nf][2], acc[mf][nf][3]);
        }
    }
}

// ---------------- inter-chunk recurrence ----------------
__global__ void chunkscan_k(const float* __restrict__ st, const float* __restrict__ acs,
                            float* __restrict__ pv) {
    int idx = blockIdx.x * blockDim.x + threadIdx.x;
    int n = idx & (DS - 1);
    int p = (idx >> 7) & (HD - 1);
    int h = (idx >> 13) & (NH - 1);
    int b = (idx >> 17) & (B_ - 1);
    int dir = idx >> 18;
    const float* std_ = st + dir * SZ_ST;
    const float* acsd = acs + dir * SZ_ACS;
    float* pvd = pv + dir * SZ_ST;
    float S = 0.f;
    for (int c = 0; c < NC; c++) {
        size_t off = ((size_t)((b * NC + c) * NH + h) * HD + p) * DS + n;
        pvd[off] = S;
        float at = acsd[(b * NH + h) * L_ + c * CH + CH - 1];
        S = S * expf(at) + std_[off];
    }
}

// ---------------- Y via tf32 mma, fully precomputed decay ----------------
__global__ void __launch_bounds__(256)
ssd_y_mma_k(const float* __restrict__ xbc, const float* __restrict__ dt,
            const float* __restrict__ acs, const float* __restrict__ cb,
            const float* __restrict__ pv,
            const float* __restrict__ Dh0, const float* __restrict__ Dh1,
            float* __restrict__ y) {
    int lt = blockIdx.x, h = blockIdx.y;
    int dir = blockIdx.z / (B_ * NC);
    int bc = blockIdx.z % (B_ * NC);
    int c = bc % NC, b = bc / NC;
    const float* xbcd = xbc + dir * SZ_XBC;
    const float* dtd  = dt  + dir * SZ_DT;
    const float* acsd = acs + dir * SZ_ACS;
    const float* Dh   = dir ? Dh1 : Dh0;
    int tid = threadIdx.x;
    int warp = tid >> 5, lane = tid & 31;
    int wm = warp >> 2, wn = warp & 3;
    int group = lane >> 2, tig = lane & 3;
    __shared__ float Ws[64][36];
    __shared__ float Xs[32][72];
    __shared__ float Ps[64][36];
    __shared__ float csl[64], el64[64], eoff[64];
    __shared__ float einv[CH];
    int l0 = lt * 64;
    int acsbase = (b * NH + h) * L_ + c * CH;
    float csl0 = acsd[acsbase + l0];
    if (tid < 64) {
        float v = acsd[acsbase + l0 + tid];
        csl[tid]  = v;
        el64[tid] = __expf(v - csl0);
        eoff[tid] = __expf(v);
    }
    einv[tid] = __expf(csl0 - acsd[acsbase + tid]);
    __syncthreads();
    const float* cbb = cb + dir * SZ_CB + (size_t)(b * NC + c) * CH * CH;
    float acc[2][2][4] = {};
    int nst = 2 * lt + 2;
    for (int stp = 0; stp < nst; stp++) {
        int s0 = stp * 32;
        bool lower = (s0 + 31 < l0);
        if (lower) {
#pragma unroll
            for (int i = 0; i < 8; i++) {
                int e = tid + i * 256;
                int j = e & 31, ii = e >> 5;
                Ws[ii][j] = tf32v(el64[ii] * einv[s0 + j] * cbb[(l0 + ii) * CH + s0 + j]);
            }
        } else {
#pragma unroll
            for (int i = 0; i < 8; i++) {
                int e = tid + i * 256;
                int j = e & 31, ii = e >> 5;
                float w = 0.f;
                if (s0 + j <= l0 + ii)
                    w = __expf(csl[ii] - acsd[acsbase + s0 + j]) * cbb[(l0 + ii) * CH + s0 + j];
                Ws[ii][j] = tf32v(w);
            }
        }
#pragma unroll
        for (int i = 0; i < 8; i++) {
            int e = tid + i * 256;
            int pp = e & 63, ss = e >> 6;
            int row = b * L_ + c * CH + s0 + ss;
            Xs[ss][pp] = tf32v(xbcd[(size_t)row * CD + h * HD + pp] * dtd[(size_t)row * NH + h]);
        }
        __syncthreads();
#pragma unroll
        for (int ks = 0; ks < 4; ks++) {
            int k0 = ks * 8;
            uint32_t af[2][4], bf[2][2];
#pragma unroll
            for (int mf = 0; mf < 2; mf++) {
                int rm = wm * 32 + mf * 16 + group;
                af[mf][0] = __float_as_uint(Ws[rm    ][k0 + tig]);
                af[mf][1] = __float_as_uint(Ws[rm + 8][k0 + tig]);
                af[mf][2] = __float_as_uint(Ws[rm    ][k0 + tig + 4]);
                af[mf][3] = __float_as_uint(Ws[rm + 8][k0 + tig + 4]);
            }
#pragma unroll
            for (int nf = 0; nf < 2; nf++) {
                int rn = wn * 16 + nf * 8 + group;
                bf[nf][0] = __float_as_uint(Xs[k0 + tig    ][rn]);
                bf[nf][1] = __float_as_uint(Xs[k0 + tig + 4][rn]);
            }
#pragma unroll
            for (int mf = 0; mf < 2; mf++)
#pragma unroll
                for (int nf = 0; nf < 2; nf++) MMA_TF32(acc[mf][nf], af[mf], bf[nf]);
        }
        __syncthreads();
    }
    const float* pvb = pv + dir * SZ_ST + (size_t)((b * NC + c) * NH + h) * HD * DS;
    for (int nt = 0; nt < 4; nt++) {
        int n0 = nt * 32;
#pragma unroll
        for (int i = 0; i < 8; i++) {
            int e = tid + i * 256;
            int j = e & 31, ii = e >> 5;
            int row = b * L_ + c * CH + l0 + ii;
            Ws[ii][j] = tf32v(xbcd[(size_t)row * CD + DI + DS + n0 + j] * eoff[ii]);
        }
#pragma unroll
        for (int i = 0; i < 8; i++) {
            int e = tid + i * 256;
            int j = e & 31, pp = e >> 5;
            Ps[pp][j] = tf32v(pvb[pp * DS + n0 + j]);
        }
        __syncthreads();
#pragma unroll
        for (int ks = 0; ks < 4; ks++) {
            int k0 = ks * 8;
            uint32_t af[2][4], bf[2][2];
#pragma unroll
            for (int mf = 0; mf < 2; mf++) {
                int rm = wm * 32 + mf * 16 + group;
                af[mf][0] = __float_as_uint(Ws[rm    ][k0 + tig]);
                af[mf][1] = __float_as_uint(Ws[rm + 8][k0 + tig]);
                af[mf][2] = __float_as_uint(Ws[rm    ][k0 + tig + 4]);
                af[mf][3] = __float_as_uint(Ws[rm + 8][k0 + tig + 4]);
            }
#pragma unroll
            for (int nf = 0; nf < 2; nf++) {
                int rn = wn * 16 + nf * 8 + group;
                bf[nf][0] = __float_as_uint(Ps[rn][k0 + tig]);
                bf[nf][1] = __float_as_uint(Ps[rn][k0 + tig + 4]);
            }
#pragma unroll
            for (int mf = 0; mf < 2; mf++)
#pragma unroll
                for (int nf = 0; nf < 2; nf++) MMA_TF32(acc[mf][nf], af[mf], bf[nf]);
        }
        __syncthreads();
    }
    float dh = Dh[h];
    float* yd = y + dir * SZ_Y;
#pragma unroll
    for (int mf = 0; mf < 2; mf++) {
#pragma unroll
        for (int nf = 0; nf < 2; nf++) {
            int ll = l0 + wm * 32 + mf * 16 + group;
            int pp = wn * 16 + nf * 8 + 2 * tig;
#pragma unroll
            for (int rr = 0; rr < 2; rr++) {
                int row = b * L_ + c * CH + ll + rr * 8;
                float2 xr = *reinterpret_cast<const float2*>(
                    xbcd + (size_t)row * CD + h * HD + pp);
                *reinterpret_cast<float2*>(yd + (size_t)row * DI + h * HD + pp) =
                    make_float2(acc[mf][nf][rr * 2 + 0] + xr.x * dh,
                                acc[mf][nf][rr * 2 + 1] + xr.y * dh);
            }
        }
    }
}

// ---------------- gating + RMSNorm (float4) ----------------
__global__ void gate_rms_k(float* __restrict__ y, const float* __restrict__ zx,
                           const float* __restrict__ nw0, const float* __restrict__ nw1) {
    int row = blockIdx.x;
    int dir = row / (B_ * L_);
    row %= B_ * L_;
    const float* nw = dir ? nw1 : nw0;
    float* yd = y + dir * SZ_Y + (size_t)row * DI;
    const float* zxd = zx + dir * SZ_ZX + (size_t)row * DIP;
    int tid = threadIdx.x;
    float4 yv = *reinterpret_cast<const float4*>(yd + tid * 4);
    float4 zv = *reinterpret_cast<const float4*>(zxd + tid * 4);
    yv.x *= siluf(zv.x); yv.y *= siluf(zv.y); yv.z *= siluf(zv.z); yv.w *= siluf(zv.w);
    float ss = yv.x * yv.x + yv.y * yv.y + yv.z * yv.z + yv.w * yv.w;
    __shared__ float sh[256];
    sh[tid] = ss;
    __syncthreads();
    for (int o = 128; o > 0; o >>= 1) {
        if (tid < o) sh[tid] += sh[tid + o];
        __syncthreads();
    }
    float scale = rsqrtf(sh[0] / DI + RMS_EPS);
    float4 wv = *reinterpret_cast<const float4*>(nw + tid * 4);
    yv.x *= scale * wv.x; yv.y *= scale * wv.y; yv.z *= scale * wv.z; yv.w *= scale * wv.w;
    *reinterpret_cast<float4*>(yd + tid * 4) = yv;
}

// ---------------- launch ----------------
extern "C" void kernel_launch(void* const* d_in, const int* in_sizes, int n_in,
                              void* d_out, int out_size) {
    (void)in_sizes; (void)n_in; (void)out_size;
    const float* x      = (const float*)d_in[0];
    const float* gn_w   = (const float*)d_in[1];
    const float* gn_b   = (const float*)d_in[2];
    const float* proj_w = (const float*)d_in[3];
    const float* proj_b = (const float*)d_in[4];
    const float* fw[8], *bw[8];
    for (int i = 0; i < 8; i++) { fw[i] = (const float*)d_in[5 + i]; bw[i] = (const float*)d_in[13 + i]; }
    float* out = (float*)d_out;

    float *t_, *zx_, *xbc_, *dt_, *acs_, *cb_, *st_, *pv_, *y_, *r_, *part_, *stats_;
    cudaGetSymbolAddress((void**)&t_,    g_t);
    cudaGetSymbolAddress((void**)&zx_,   g_zx);
    cudaGetSymbolAddress((void**)&xbc_,  g_xbc);
    cudaGetSymbolAddress((void**)&dt_,   g_dt);
    cudaGetSymbolAddress((void**)&acs_,  g_acs);
    cudaGetSymbolAddress((void**)&cb_,   g_cb);
    cudaGetSymbolAddress((void**)&st_,   g_st);
    cudaGetSymbolAddress((void**)&pv_,   g_pv);
    cudaGetSymbolAddress((void**)&y_,    g_y);
    cudaGetSymbolAddress((void**)&r_,    g_r);
    cudaGetSymbolAddress((void**)&part_, g_part);
    cudaGetSymbolAddress((void**)&stats_,g_stats);

    gn_part_k<<<dim3(64, B_), 256>>>(x, part_);
    gn_fin_k<<<B_, 64>>>(part_, stats_);
    gn_apply_k<<<dim3(L_ / 32, DM / 32, B_), dim3(32, 8)>>>(x, gn_w, gn_b, stats_, t_);

    gemm_tf32<128,128,0><<<dim3((DIP + 127) / 128, (B_ * L_) / 128, 2), 256>>>(
        t_, fw[0], bw[0], zx_, B_ * L_, DIP, DM, DM, DM, DIP,
        0, 0, 0, 1, 0, SZ_ZX, L_, nullptr, nullptr);

    conv_silu_k<<<(int)((2LL * B_ * L_ * (CD / 4) + 255) / 256), 256>>>(
        zx_, fw[1], fw[2], bw[1], bw[2], xbc_);
    dt_scan_k<<<2 * B_ * NH * NC, CH>>>(zx_, fw[3], fw[4], bw[3], bw[4], dt_, acs_);

    gemm_tf32<128,64,0><<<dim3(CH / 64, CH / 128, 2 * B_ * NC), 256>>>(
        xbc_ + DI + DS, xbc_ + DI, xbc_ + SZ_XBC + DI, cb_, CH, CH, DS, CD, CD, CH,
        (long long)CH * CD, (long long)CH * CD, (long long)CH * CH,
        B_ * NC, SZ_XBC, SZ_CB, 0, nullptr, nullptr);

    states_mma_k<<<dim3(NH, NC, 2 * B_), 256>>>(xbc_, dt_, acs_, st_);
    chunkscan_k<<<(2 * B_ * NH * HD * DS) / 256, 256>>>(st_, acs_, pv_);
    ssd_y_mma_k<<<dim3(CH / 64, NH, 2 * B_ * NC), 256>>>(
        xbc_, dt_, acs_, cb_, pv_, fw[5], bw[5], y_);
    gate_rms_k<<<2 * B_ * L_, 256>>>(y_, zx_, fw[6], bw[6]);

    gemm_tf32<128,64,1><<<dim3(DM / 64, (B_ * L_) / 128, 2), 256>>>(
        y_, fw[7], bw[7], r_, B_ * L_, DM, DI, DI, DI, DM,
        0, 0, 0, 1, SZ_Y, 0, 0, t_, nullptr);

    gemm_tf32<128,64,2><<<dim3(DM / 64, (B_ * L_) / 128, 1), 256>>>(
        r_, proj_w, proj_w, out, B_ * L_, DM, 2 * DM, 2 * DM, 2 * DM, DM,
        0, 0, 0, 1, 0, 0, 0, x, proj_b);
}